// round 1
// baseline (speedup 1.0000x reference)
#include <cuda_runtime.h>
#include <math.h>

#define LN_EPS 1e-5f
#define NEG_FILL -1.0e9f

// ---------------- device scratch (no allocations allowed) ----------------
#define MAXB 8192
__device__ unsigned g_gf_enc[MAXB * 128];  // segment-max pooled features (order-encoded)
__device__ float    g_score[MAXB];         // decision-net scores before EMA normalization

// Monotone order-preserving float->uint encoding so atomicMax works for floats.
__device__ __forceinline__ unsigned enc_f(float f) {
    int i = __float_as_int(f);
    unsigned u = (unsigned)i;
    return (i < 0) ? ~u : (u | 0x80000000u);
}
__device__ __forceinline__ float dec_f(unsigned u) {
    return (u & 0x80000000u) ? __int_as_float((int)(u & 0x7FFFFFFFu))
                             : __int_as_float((int)(~u));
}
__device__ __forceinline__ float lrelu(float v) { return v >= 0.0f ? v : 0.2f * v; }

// ---------------- kernel A: init pooled buffer to -1e9 ----------------
__global__ void k_init(int n) {
    int i = blockIdx.x * blockDim.x + threadIdx.x;
    if (i < n) g_gf_enc[i] = enc_f(NEG_FILL);
}

// ---------------- kernel B: fused point net + segment max ----------------
// Block: 256 threads, processes 128 consecutive muon rows.
// Stage 1: layer1 (7->64) + LN + lrelu, per warp (16 rows each), result stored
//          transposed in shared H1T[k][row].
// Stage 2: tiled GEMM 128x128x64 (8x8 register tile per thread) = layer2.
// Stage 3: LN over 128 cols + lrelu + nan guard, then run-length segment max
//          (batch_index is sorted) with atomicMax flushes.
#define TB 256
#define ROWS 128

__global__ __launch_bounds__(256) void k_main(
    const float* __restrict__ muons, const int* __restrict__ bidx,
    const float* __restrict__ cond,
    const float* __restrict__ w1, const float* __restrict__ b1,
    const float* __restrict__ g1, const float* __restrict__ be1,
    const float* __restrict__ w2, const float* __restrict__ b2,
    const float* __restrict__ g2, const float* __restrict__ be2,
    int N)
{
    extern __shared__ float sm[];
    float* W1  = sm;              // 7*64 = 448
    float* B1s = W1 + 448;        // 64
    float* G1s = B1s + 64;        // 64
    float* BE1s= G1s + 64;        // 64
    float* B2s = BE1s + 64;       // 128
    float* G2s = B2s + 128;       // 128
    float* BE2s= G2s + 128;       // 128
    int*   SBI = (int*)(BE2s + 128);       // 128 ints
    float* W2s = (float*)(SBI + 128);      // 64*128 = 8192
    float* H1T = W2s + 8192;               // 64*132 = 8448 (pitch 132)
    // regions reused after stage 2:
    float* REDS  = W2s;                    // 16*128
    float* REDQ  = W2s + 2048;             // 16*128
    float* RMEAN = W2s + 4096;             // 128
    float* RRSTD = RMEAN + 128;            // 128
    float* SVAL  = H1T;                    // 64*132 (per 64-row chunk)

    const int tid  = threadIdx.x;
    const int lane = tid & 31;
    const int wrp  = tid >> 5;
    const int base = blockIdx.x * ROWS;

    // ---- cooperative weight load ----
    for (int i = tid; i < 448;  i += TB) W1[i]  = w1[i];
    for (int i = tid; i < 64;   i += TB) { B1s[i] = b1[i]; G1s[i] = g1[i]; BE1s[i] = be1[i]; }
    for (int i = tid; i < 128;  i += TB) { B2s[i] = b2[i]; G2s[i] = g2[i]; BE2s[i] = be2[i]; }
    for (int i = tid; i < 8192; i += TB) W2s[i] = w2[i];
    if (tid < 128) {
        int r = base + tid;
        SBI[tid] = (r < N) ? bidx[r] : -1;
    }
    __syncthreads();

    // ---- stage 1: layer1 + LN(64) + lrelu, transposed store ----
    #pragma unroll 1
    for (int i = 0; i < 16; i++) {
        int lr = wrp * 16 + i;
        int r  = base + lr;
        float x[7] = {0.f,0.f,0.f,0.f,0.f,0.f,0.f};
        if (r < N) {
            x[0] = muons[3*r]; x[1] = muons[3*r+1]; x[2] = muons[3*r+2];
            int bi = SBI[lr];
            const float4 c4 = *(const float4*)(cond + 4*bi);
            x[3] = c4.x; x[4] = c4.y; x[5] = c4.z; x[6] = c4.w;
        }
        float oa = B1s[lane], ob = B1s[lane + 32];
        #pragma unroll
        for (int j = 0; j < 7; j++) {
            oa = fmaf(x[j], W1[j*64 + lane],      oa);
            ob = fmaf(x[j], W1[j*64 + lane + 32], ob);
        }
        float s = oa + ob;
        float q = oa*oa + ob*ob;
        #pragma unroll
        for (int d = 16; d; d >>= 1) {
            s += __shfl_xor_sync(0xFFFFFFFFu, s, d);
            q += __shfl_xor_sync(0xFFFFFFFFu, q, d);
        }
        float m    = s * (1.0f/64.0f);
        float var  = fmaf(-m, m, q * (1.0f/64.0f));
        float rstd = rsqrtf(var + LN_EPS);
        float ha = lrelu(fmaf((oa - m) * rstd, G1s[lane],      BE1s[lane]));
        float hb = lrelu(fmaf((ob - m) * rstd, G1s[lane + 32], BE1s[lane + 32]));
        if (r >= N) { ha = 0.f; hb = 0.f; }
        H1T[lane*132 + lr]        = ha;
        H1T[(lane+32)*132 + lr]   = hb;
    }
    __syncthreads();

    // ---- stage 2: GEMM 128x128x64 ----
    const int rg = tid & 15;         // row group
    const int cg = tid >> 4;         // col group
    const int r0 = rg * 8;
    const int c0 = cg * 8;

    float acc[8][8];
    #pragma unroll
    for (int i = 0; i < 8; i++)
        #pragma unroll
        for (int j = 0; j < 8; j++) acc[i][j] = B2s[c0 + j];

    #pragma unroll 8
    for (int k = 0; k < 64; k++) {
        float4 a0 = *(const float4*)(H1T + k*132 + r0);
        float4 a1 = *(const float4*)(H1T + k*132 + r0 + 4);
        float4 w0 = *(const float4*)(W2s + k*128 + c0);
        float4 w1v= *(const float4*)(W2s + k*128 + c0 + 4);
        float a[8] = {a0.x,a0.y,a0.z,a0.w,a1.x,a1.y,a1.z,a1.w};
        float b[8] = {w0.x,w0.y,w0.z,w0.w,w1v.x,w1v.y,w1v.z,w1v.w};
        #pragma unroll
        for (int i = 0; i < 8; i++)
            #pragma unroll
            for (int j = 0; j < 8; j++)
                acc[i][j] = fmaf(a[i], b[j], acc[i][j]);
    }
    __syncthreads();   // done reading W2s/H1T; regions may be reused

    // ---- stage 3a: LN(128) statistics ----
    #pragma unroll
    for (int i = 0; i < 8; i++) {
        float ps = 0.f, pq = 0.f;
        #pragma unroll
        for (int j = 0; j < 8; j++) { ps += acc[i][j]; pq = fmaf(acc[i][j], acc[i][j], pq); }
        REDS[cg*128 + r0 + i] = ps;
        REDQ[cg*128 + r0 + i] = pq;
    }
    __syncthreads();
    if (tid < 128) {
        float s = 0.f, q = 0.f;
        #pragma unroll
        for (int c = 0; c < 16; c++) { s += REDS[c*128 + tid]; q += REDQ[c*128 + tid]; }
        float m   = s * (1.0f/128.0f);
        float var = fmaf(-m, m, q * (1.0f/128.0f));
        RMEAN[tid] = m;
        RRSTD[tid] = rsqrtf(var + LN_EPS);
    }
    __syncthreads();

    // ---- stage 3b: apply LN + lrelu + nan guard in registers ----
    float g2v[8], be2v[8];
    #pragma unroll
    for (int j = 0; j < 8; j++) { g2v[j] = G2s[c0+j]; be2v[j] = BE2s[c0+j]; }
    #pragma unroll
    for (int i = 0; i < 8; i++) {
        float m  = RMEAN[r0 + i];
        float rs = RRSTD[r0 + i];
        #pragma unroll
        for (int j = 0; j < 8; j++) {
            float v = fmaf((acc[i][j] - m) * rs, g2v[j], be2v[j]);
            v = lrelu(v);
            if (!isfinite(v)) v = 0.f;
            acc[i][j] = v;
        }
    }
    __syncthreads();

    // ---- stage 3c: segment max via two 64-row chunks (reuse H1T as SVAL) ----
    #pragma unroll 1
    for (int chunk = 0; chunk < 2; chunk++) {
        int cb = chunk * 64;
        bool mine = (chunk == 0) ? (rg < 8) : (rg >= 8);
        if (mine) {
            #pragma unroll
            for (int i = 0; i < 8; i++)
                #pragma unroll
                for (int j = 0; j < 8; j++)
                    SVAL[(r0 + i - cb)*132 + c0 + j] = acc[i][j];
        }
        __syncthreads();
        {
            int c  = tid & 127;
            int rb = (tid >> 7) * 32;  // 0 or 32
            float cur  = -3.0e38f;
            int  curbi = SBI[cb + rb];
            #pragma unroll 1
            for (int rr = 0; rr < 32; rr++) {
                int lr = cb + rb + rr;
                int bi = SBI[lr];
                float v = SVAL[(rb + rr)*132 + c];
                if (bi != curbi) {
                    if (curbi >= 0) atomicMax(&g_gf_enc[curbi*128 + c], enc_f(cur));
                    curbi = bi; cur = v;
                } else {
                    cur = fmaxf(cur, v);
                }
            }
            if (curbi >= 0) atomicMax(&g_gf_enc[curbi*128 + c], enc_f(cur));
        }
        __syncthreads();
    }
}

// ---------------- kernel C: decision net, warp per row ----------------
__global__ __launch_bounds__(256) void k_dec(
    const float* __restrict__ cond,
    const float* __restrict__ w3, const float* __restrict__ b3,
    const float* __restrict__ g3, const float* __restrict__ be3,
    const float* __restrict__ w4, const float* __restrict__ b4,
    const float* __restrict__ g4, const float* __restrict__ be4,
    const float* __restrict__ w5, const float* __restrict__ b5,
    int B)
{
    extern __shared__ float sm[];
    float* W3 = sm;               // 132*128 = 16896
    float* W4 = W3 + 16896;       // 128*64 = 8192
    float* W5 = W4 + 8192;        // 64
    float* B3 = W5 + 64;          // 128
    float* G3 = B3 + 128;
    float* BE3= G3 + 128;
    float* B4 = BE3 + 128;        // 64
    float* G4 = B4 + 64;
    float* BE4= G4 + 64;
    float* XB = BE4 + 64;         // 8 * 136

    const int tid = threadIdx.x, lane = tid & 31, wrp = tid >> 5;
    for (int i = tid; i < 16896; i += 256) W3[i] = w3[i];
    for (int i = tid; i < 8192;  i += 256) W4[i] = w4[i];
    for (int i = tid; i < 64;    i += 256) { W5[i] = w5[i]; B4[i] = b4[i]; G4[i] = g4[i]; BE4[i] = be4[i]; }
    for (int i = tid; i < 128;   i += 256) { B3[i] = b3[i]; G3[i] = g3[i]; BE3[i] = be3[i]; }
    __syncthreads();

    float* xb = XB + wrp * 136;
    const float b5v = b5[0];

    #pragma unroll 1
    for (int i = 0; i < 4; i++) {
        int row = (blockIdx.x * 8 + wrp) * 4 + i;
        if (row >= B) break;
        __syncwarp();
        // gather pooled features (+ second nan_to_num) and conditions
        #pragma unroll
        for (int j = 0; j < 4; j++) {
            float v = dec_f(g_gf_enc[row*128 + lane + 32*j]);
            if (isnan(v)) v = NEG_FILL;
            else if (isinf(v)) v = (v > 0.f) ? 1.0e9f : NEG_FILL;
            xb[lane + 32*j] = v;
        }
        if (lane < 4) xb[128 + lane] = cond[row*4 + lane];
        __syncwarp();

        // layer3: 132 -> 128
        float a0 = B3[lane], a1 = B3[lane+32], a2 = B3[lane+64], a3 = B3[lane+96];
        #pragma unroll 4
        for (int k = 0; k < 132; k++) {
            float xk = xb[k];
            const float* wr = W3 + k*128;
            a0 = fmaf(xk, wr[lane],      a0);
            a1 = fmaf(xk, wr[lane+32],   a1);
            a2 = fmaf(xk, wr[lane+64],   a2);
            a3 = fmaf(xk, wr[lane+96],   a3);
        }
        float s = a0+a1+a2+a3;
        float q = a0*a0 + a1*a1 + a2*a2 + a3*a3;
        #pragma unroll
        for (int d = 16; d; d >>= 1) {
            s += __shfl_xor_sync(0xFFFFFFFFu, s, d);
            q += __shfl_xor_sync(0xFFFFFFFFu, q, d);
        }
        float m = s * (1.0f/128.0f);
        float var = fmaf(-m, m, q * (1.0f/128.0f));
        float rs = rsqrtf(var + LN_EPS);
        a0 = lrelu(fmaf((a0-m)*rs, G3[lane],    BE3[lane]));
        a1 = lrelu(fmaf((a1-m)*rs, G3[lane+32], BE3[lane+32]));
        a2 = lrelu(fmaf((a2-m)*rs, G3[lane+64], BE3[lane+64]));
        a3 = lrelu(fmaf((a3-m)*rs, G3[lane+96], BE3[lane+96]));
        __syncwarp();
        xb[lane] = a0; xb[lane+32] = a1; xb[lane+64] = a2; xb[lane+96] = a3;
        __syncwarp();

        // layer4: 128 -> 64
        float c0v = B4[lane], c1v = B4[lane+32];
        #pragma unroll 4
        for (int k = 0; k < 128; k++) {
            float xk = xb[k];
            c0v = fmaf(xk, W4[k*64 + lane],      c0v);
            c1v = fmaf(xk, W4[k*64 + lane + 32], c1v);
        }
        s = c0v + c1v;
        q = c0v*c0v + c1v*c1v;
        #pragma unroll
        for (int d = 16; d; d >>= 1) {
            s += __shfl_xor_sync(0xFFFFFFFFu, s, d);
            q += __shfl_xor_sync(0xFFFFFFFFu, q, d);
        }
        m = s * (1.0f/64.0f);
        var = fmaf(-m, m, q * (1.0f/64.0f));
        rs = rsqrtf(var + LN_EPS);
        c0v = lrelu(fmaf((c0v-m)*rs, G4[lane],    BE4[lane]));
        c1v = lrelu(fmaf((c1v-m)*rs, G4[lane+32], BE4[lane+32]));

        // layer5: 64 -> 1
        float p = c0v * W5[lane] + c1v * W5[lane+32];
        #pragma unroll
        for (int d = 16; d; d >>= 1) p += __shfl_xor_sync(0xFFFFFFFFu, p, d);
        if (lane == 0) g_score[row] = p + b5v;
    }
}

// ---------------- kernel D: EMA normalize + tanh ----------------
__global__ void k_final(float* __restrict__ out, int B) {
    __shared__ float red[1024];
    int tid = threadIdx.x;
    float s = 0.f;
    for (int i = tid; i < B; i += 1024) s += fabsf(g_score[i]);
    red[tid] = s;
    __syncthreads();
    #pragma unroll
    for (int d = 512; d; d >>= 1) {
        if (tid < d) red[tid] += red[tid + d];
        __syncthreads();
    }
    float mean  = red[0] / (float)B;
    float ema   = 0.99f + 0.01f * mean;
    float denom = fmaxf(ema, 0.1f);
    for (int i = tid; i < B; i += 1024) {
        float sc = g_score[i] / denom;
        sc = fminf(fmaxf(sc, -5.0f), 5.0f);
        out[i] = 10.0f * tanhf(sc * 0.2f);
    }
}

// ---------------- launch ----------------
extern "C" void kernel_launch(void* const* d_in, const int* in_sizes, int n_in,
                              void* d_out, int out_size) {
    const float* muons = (const float*)d_in[0];
    const int*   bidx  = (const int*)  d_in[1];
    const float* cond  = (const float*)d_in[2];
    // d_in[3] = batch_size scalar on device (unused; derived from sizes)
    const float* w1  = (const float*)d_in[4];
    const float* b1  = (const float*)d_in[5];
    const float* g1  = (const float*)d_in[6];
    const float* be1 = (const float*)d_in[7];
    const float* w2  = (const float*)d_in[8];
    const float* b2  = (const float*)d_in[9];
    const float* g2  = (const float*)d_in[10];
    const float* be2 = (const float*)d_in[11];
    const float* w3  = (const float*)d_in[12];
    const float* b3  = (const float*)d_in[13];
    const float* g3  = (const float*)d_in[14];
    const float* be3 = (const float*)d_in[15];
    const float* w4  = (const float*)d_in[16];
    const float* b4  = (const float*)d_in[17];
    const float* g4  = (const float*)d_in[18];
    const float* be4 = (const float*)d_in[19];
    const float* w5  = (const float*)d_in[20];
    const float* b5  = (const float*)d_in[21];

    int N = in_sizes[0] / 3;
    int B = in_sizes[2] / 4;
    if (B > MAXB) B = MAXB;

    static const size_t SMEM_MAIN = (size_t)(448 + 64*3 + 128*3 + 128 + 8192 + 64*132) * 4;
    static const size_t SMEM_DEC  = (size_t)(16896 + 8192 + 64 + 128*3 + 64*3 + 8*136) * 4;
    cudaFuncSetAttribute(k_main, cudaFuncAttributeMaxDynamicSharedMemorySize, (int)SMEM_MAIN);
    cudaFuncSetAttribute(k_dec,  cudaFuncAttributeMaxDynamicSharedMemorySize, (int)SMEM_DEC);

    int initN = B * 128;
    k_init<<<(initN + 255) / 256, 256>>>(initN);

    int nBlocks = (N + ROWS - 1) / ROWS;
    k_main<<<nBlocks, TB, SMEM_MAIN>>>(muons, bidx, cond,
                                       w1, b1, g1, be1, w2, b2, g2, be2, N);

    int decBlocks = (B + 31) / 32;
    k_dec<<<decBlocks, 256, SMEM_DEC>>>(cond, w3, b3, g3, be3,
                                        w4, b4, g4, be4, w5, b5, B);

    k_final<<<1, 1024>>>((float*)d_out, B);
}

// round 4
// speedup vs baseline: 1.5839x; 1.5839x over previous
#include <cuda_runtime.h>
#include <math.h>
#include <cstdint>

#define LN_EPS 1e-5f
#define NEG_FILL -1.0e9f
#define MAXB 8192

// ---------------- device scratch ----------------
__device__ unsigned g_gf_enc[MAXB * 128];
__device__ float    g_score[MAXB];

// ---------------- helpers ----------------
__device__ __forceinline__ unsigned enc_f(float f) {
    int i = __float_as_int(f);
    unsigned u = (unsigned)i;
    return (i < 0) ? ~u : (u | 0x80000000u);
}
__device__ __forceinline__ float dec_f(unsigned u) {
    return (u & 0x80000000u) ? __int_as_float((int)(u & 0x7FFFFFFFu))
                             : __int_as_float((int)(~u));
}
__device__ __forceinline__ float lrelu(float v) { return v >= 0.0f ? v : 0.2f * v; }
__device__ __forceinline__ uint32_t f2tf32(float f) {
    uint32_t u;
    asm("cvt.rna.tf32.f32 %0, %1;" : "=r"(u) : "f"(f));
    return u;
}

// tf32 warp MMA: D(16x8) += A(16x8) * B(8x8)
__device__ __forceinline__ void mma_tf32(float& c0, float& c1, float& c2, float& c3,
                                         uint32_t a0, uint32_t a1, uint32_t a2, uint32_t a3,
                                         uint32_t b0, uint32_t b1) {
    asm volatile(
        "mma.sync.aligned.m16n8k8.row.col.f32.tf32.tf32.f32 "
        "{%0,%1,%2,%3}, {%4,%5,%6,%7}, {%8,%9}, {%0,%1,%2,%3};"
        : "+f"(c0), "+f"(c1), "+f"(c2), "+f"(c3)
        : "r"(a0), "r"(a1), "r"(a2), "r"(a3), "r"(b0), "r"(b1));
}

// ---------------- kernel A: init pooled buffer ----------------
__global__ void k_init(int n) {
    int i = blockIdx.x * blockDim.x + threadIdx.x;
    if (i < n) g_gf_enc[i] = enc_f(NEG_FILL);
}

// ---------------- k_main: persistent fused point-net (tf32 mma.sync) -------
// smem layout (bytes):
//   [0, 66048)          region0: A tf32 [128][76]  (38912 B)   | later SVAL fp32 [128][129]
//   [66048, 100864)     B tf32 [n=128][k=68 pitch] (34816 B)
//   [100864, 109056)    params: W1 448|B1 64|G1 64|BE1 64|B2 128|G2 128|BE2 128|SBI 128|Xs 384|Cs 512
#define TB 256
#define ROWS 128
#define A_PITCH 76
#define B_PITCH 68
#define SV_PITCH 129
#define OFF_B    66048
#define OFF_PARM 100864
#define SMEM_NEED (OFF_PARM + 8192)

__global__ __launch_bounds__(256) void k_main(
    const float* __restrict__ muons, const int* __restrict__ bidx,
    const float* __restrict__ cond,
    const float* __restrict__ w1, const float* __restrict__ b1,
    const float* __restrict__ g1, const float* __restrict__ be1,
    const float* __restrict__ w2, const float* __restrict__ b2,
    const float* __restrict__ g2, const float* __restrict__ be2,
    int N, int nTiles)
{
    extern __shared__ char base[];
    uint32_t* const Au   = (uint32_t*)(base);            // A operand (tf32 bits)
    float*    const SVAL = (float*)(base);               // reused post-MMA
    uint32_t* const Bu   = (uint32_t*)(base + OFF_B);    // B operand (tf32 bits)
    float*    const PR   = (float*)(base + OFF_PARM);
    float* const W1   = PR;          // 448
    float* const B1s  = W1 + 448;    // 64
    float* const G1s  = B1s + 64;    // 64
    float* const BE1s = G1s + 64;    // 64
    float* const B2s  = BE1s + 64;   // 128 (float2-aligned)
    float* const G2s  = B2s + 128;   // 128
    float* const BE2s = G2s + 128;   // 128
    int*   const SBI  = (int*)(BE2s + 128);  // 128
    float* const Xs   = (float*)(SBI + 128); // 384 (muon features)
    float* const Cs   = Xs + 384;            // 512 (gathered conditions)

    const int tid  = threadIdx.x;
    const int lane = tid & 31;
    const int wrp  = tid >> 5;
    const int quad = lane >> 2;   // 0..7
    const int tig  = lane & 3;    // 0..3

    // ---- one-time: params + B operand ----
    for (int i = tid; i < 448; i += TB) W1[i] = w1[i];
    for (int i = tid; i < 64;  i += TB) { B1s[i] = b1[i]; G1s[i] = g1[i]; BE1s[i] = be1[i]; }
    for (int i = tid; i < 128; i += TB) { B2s[i] = b2[i]; G2s[i] = g2[i]; BE2s[i] = be2[i]; }
    // B[n][k] = w2[k*128+n]
    for (int i = tid; i < 8192; i += TB) {
        int n = i & 127, k = i >> 7;
        Bu[n * B_PITCH + k] = f2tf32(w2[k * 128 + n]);
    }
    __syncthreads();

    for (int tile = blockIdx.x; tile < nTiles; tile += gridDim.x) {
        const int rbase = tile * ROWS;

        // ---- stage 0: stage inputs into smem (one latency round-trip) ----
        if (tid < 128) {
            int r = rbase + tid;
            int bi = (r < N) ? bidx[r] : -1;
            SBI[tid] = bi;
            float4 c4 = (bi >= 0) ? *(const float4*)(cond + 4 * bi)
                                  : make_float4(0.f, 0.f, 0.f, 0.f);
            *(float4*)(Cs + tid * 4) = c4;
        }
        for (int i = tid; i < 384; i += TB) {
            int gi = rbase * 3 + i;
            Xs[i] = (gi < 3 * N) ? muons[gi] : 0.f;
        }
        __syncthreads();

        // ---- stage 1: layer1 (7->64) + LN(64) + lrelu -> A[row][k] tf32 ----
        #pragma unroll 1
        for (int i = 0; i < 16; i++) {
            int lr = wrp * 16 + i;
            float x0 = Xs[lr*3], x1 = Xs[lr*3+1], x2 = Xs[lr*3+2];
            float x3 = Cs[lr*4], x4 = Cs[lr*4+1], x5 = Cs[lr*4+2], x6 = Cs[lr*4+3];
            float oa = B1s[lane], ob = B1s[lane + 32];
            oa = fmaf(x0, W1[0*64+lane], oa);      ob = fmaf(x0, W1[0*64+lane+32], ob);
            oa = fmaf(x1, W1[1*64+lane], oa);      ob = fmaf(x1, W1[1*64+lane+32], ob);
            oa = fmaf(x2, W1[2*64+lane], oa);      ob = fmaf(x2, W1[2*64+lane+32], ob);
            oa = fmaf(x3, W1[3*64+lane], oa);      ob = fmaf(x3, W1[3*64+lane+32], ob);
            oa = fmaf(x4, W1[4*64+lane], oa);      ob = fmaf(x4, W1[4*64+lane+32], ob);
            oa = fmaf(x5, W1[5*64+lane], oa);      ob = fmaf(x5, W1[5*64+lane+32], ob);
            oa = fmaf(x6, W1[6*64+lane], oa);      ob = fmaf(x6, W1[6*64+lane+32], ob);
            float s = oa + ob, q = oa*oa + ob*ob;
            #pragma unroll
            for (int d = 16; d; d >>= 1) {
                s += __shfl_xor_sync(0xFFFFFFFFu, s, d);
                q += __shfl_xor_sync(0xFFFFFFFFu, q, d);
            }
            float m    = s * (1.0f/64.0f);
            float var  = fmaf(-m, m, q * (1.0f/64.0f));
            float rstd = rsqrtf(var + LN_EPS);
            float ha = lrelu(fmaf((oa - m) * rstd, G1s[lane],      BE1s[lane]));
            float hb = lrelu(fmaf((ob - m) * rstd, G1s[lane + 32], BE1s[lane + 32]));
            Au[lr * A_PITCH + lane]      = f2tf32(ha);
            Au[lr * A_PITCH + lane + 32] = f2tf32(hb);
        }
        __syncwarp();   // A rows of this warp complete; stage 2 reads are warp-local

        // ---- stage 2: GEMM 16x128x64 per warp via mma.sync tf32 ----
        float acc[16][4];
        #pragma unroll
        for (int nt = 0; nt < 16; nt++)
            #pragma unroll
            for (int c = 0; c < 4; c++) acc[nt][c] = 0.f;

        const uint32_t* ar0 = Au + (wrp * 16 + quad) * A_PITCH + tig;
        const uint32_t* ar1 = ar0 + 8 * A_PITCH;
        const uint32_t* bp0 = Bu + quad * B_PITCH + tig;
        #pragma unroll
        for (int ks = 0; ks < 8; ks++) {
            const int k0 = ks * 8;
            uint32_t a0 = ar0[k0], a1 = ar1[k0], a2 = ar0[k0 + 4], a3 = ar1[k0 + 4];
            #pragma unroll
            for (int nt = 0; nt < 16; nt++) {
                uint32_t b0 = bp0[nt * 8 * B_PITCH + k0];
                uint32_t b1 = bp0[nt * 8 * B_PITCH + k0 + 4];
                mma_tf32(acc[nt][0], acc[nt][1], acc[nt][2], acc[nt][3],
                         a0, a1, a2, a3, b0, b1);
            }
        }
        __syncthreads();   // everyone done reading A before SVAL overwrites it

        // ---- stage 3a: bias + LN(128) stats (quad-local) ----
        float sA = 0.f, qA = 0.f, sB = 0.f, qB = 0.f;
        #pragma unroll
        for (int nt = 0; nt < 16; nt++) {
            int col = nt * 8 + tig * 2;
            float2 bb = *(const float2*)(B2s + col);
            acc[nt][0] += bb.x; acc[nt][1] += bb.y;
            acc[nt][2] += bb.x; acc[nt][3] += bb.y;
            sA += acc[nt][0] + acc[nt][1];
            qA = fmaf(acc[nt][0], acc[nt][0], fmaf(acc[nt][1], acc[nt][1], qA));
            sB += acc[nt][2] + acc[nt][3];
            qB = fmaf(acc[nt][2], acc[nt][2], fmaf(acc[nt][3], acc[nt][3], qB));
        }
        #pragma unroll
        for (int d = 1; d <= 2; d <<= 1) {
            sA += __shfl_xor_sync(0xFFFFFFFFu, sA, d);
            qA += __shfl_xor_sync(0xFFFFFFFFu, qA, d);
            sB += __shfl_xor_sync(0xFFFFFFFFu, sB, d);
            qB += __shfl_xor_sync(0xFFFFFFFFu, qB, d);
        }
        float mA  = sA * (1.0f/128.0f);
        float rsA = rsqrtf(fmaf(-mA, mA, qA * (1.0f/128.0f)) + LN_EPS);
        float mB  = sB * (1.0f/128.0f);
        float rsB = rsqrtf(fmaf(-mB, mB, qB * (1.0f/128.0f)) + LN_EPS);

        // ---- stage 3b: normalize + lrelu + nan guard -> SVAL ----
        const int ra = wrp * 16 + quad;
        const int rb = ra + 8;
        #pragma unroll
        for (int nt = 0; nt < 16; nt++) {
            int col = nt * 8 + tig * 2;
            float2 gg = *(const float2*)(G2s + col);
            float2 ee = *(const float2*)(BE2s + col);
            float v0 = lrelu(fmaf((acc[nt][0] - mA) * rsA, gg.x, ee.x));
            float v1 = lrelu(fmaf((acc[nt][1] - mA) * rsA, gg.y, ee.y));
            float v2 = lrelu(fmaf((acc[nt][2] - mB) * rsB, gg.x, ee.x));
            float v3 = lrelu(fmaf((acc[nt][3] - mB) * rsB, gg.y, ee.y));
            if (!isfinite(v0)) v0 = 0.f;
            if (!isfinite(v1)) v1 = 0.f;
            if (!isfinite(v2)) v2 = 0.f;
            if (!isfinite(v3)) v3 = 0.f;
            SVAL[ra * SV_PITCH + col]     = v0;
            SVAL[ra * SV_PITCH + col + 1] = v1;
            SVAL[rb * SV_PITCH + col]     = v2;
            SVAL[rb * SV_PITCH + col + 1] = v3;
        }
        __syncthreads();

        // ---- stage 3c: run-length segment max (sorted batch_index) ----
        {
            int c  = tid & 127;
            int r0 = (tid >> 7) * 64;
            float cur = -3.0e38f;
            int curbi = SBI[r0];
            #pragma unroll 1
            for (int rr = 0; rr < 64; rr++) {
                int lrow = r0 + rr;
                int bi = SBI[lrow];
                float v = SVAL[lrow * SV_PITCH + c];
                if (bi != curbi) {
                    if (curbi >= 0) atomicMax(&g_gf_enc[curbi * 128 + c], enc_f(cur));
                    curbi = bi; cur = v;
                } else {
                    cur = fmaxf(cur, v);
                }
            }
            if (curbi >= 0) atomicMax(&g_gf_enc[curbi * 128 + c], enc_f(cur));
        }
        __syncthreads();   // SVAL/A + SBI reuse barrier for next tile
    }
}

// ---------------- kernel C: decision net ----------------
__global__ __launch_bounds__(256) void k_dec(
    const float* __restrict__ cond,
    const float* __restrict__ w3, const float* __restrict__ b3,
    const float* __restrict__ g3, const float* __restrict__ be3,
    const float* __restrict__ w4, const float* __restrict__ b4,
    const float* __restrict__ g4, const float* __restrict__ be4,
    const float* __restrict__ w5, const float* __restrict__ b5,
    int B)
{
    extern __shared__ float sm[];
    float* W3 = sm;
    float* W4 = W3 + 16896;
    float* W5 = W4 + 8192;
    float* B3 = W5 + 64;
    float* G3 = B3 + 128;
    float* BE3= G3 + 128;
    float* B4 = BE3 + 128;
    float* G4 = B4 + 64;
    float* BE4= G4 + 64;
    float* XB = BE4 + 64;

    const int tid = threadIdx.x, lane = tid & 31, wrp = tid >> 5;
    for (int i = tid; i < 16896; i += 256) W3[i] = w3[i];
    for (int i = tid; i < 8192;  i += 256) W4[i] = w4[i];
    for (int i = tid; i < 64;    i += 256) { W5[i] = w5[i]; B4[i] = b4[i]; G4[i] = g4[i]; BE4[i] = be4[i]; }
    for (int i = tid; i < 128;   i += 256) { B3[i] = b3[i]; G3[i] = g3[i]; BE3[i] = be3[i]; }
    __syncthreads();

    float* xb = XB + wrp * 136;
    const float b5v = b5[0];

    #pragma unroll 1
    for (int i = 0; i < 4; i++) {
        int row = (blockIdx.x * 8 + wrp) * 4 + i;
        if (row >= B) break;
        __syncwarp();
        #pragma unroll
        for (int j = 0; j < 4; j++) {
            float v = dec_f(g_gf_enc[row*128 + lane + 32*j]);
            if (isnan(v)) v = NEG_FILL;
            else if (isinf(v)) v = (v > 0.f) ? 1.0e9f : NEG_FILL;
            xb[lane + 32*j] = v;
        }
        if (lane < 4) xb[128 + lane] = cond[row*4 + lane];
        __syncwarp();

        float a0 = B3[lane], a1 = B3[lane+32], a2 = B3[lane+64], a3 = B3[lane+96];
        #pragma unroll 4
        for (int k = 0; k < 132; k++) {
            float xk = xb[k];
            const float* wr = W3 + k*128;
            a0 = fmaf(xk, wr[lane],      a0);
            a1 = fmaf(xk, wr[lane+32],   a1);
            a2 = fmaf(xk, wr[lane+64],   a2);
            a3 = fmaf(xk, wr[lane+96],   a3);
        }
        float s = a0+a1+a2+a3;
        float q = a0*a0 + a1*a1 + a2*a2 + a3*a3;
        #pragma unroll
        for (int d = 16; d; d >>= 1) {
            s += __shfl_xor_sync(0xFFFFFFFFu, s, d);
            q += __shfl_xor_sync(0xFFFFFFFFu, q, d);
        }
        float m = s * (1.0f/128.0f);
        float var = fmaf(-m, m, q * (1.0f/128.0f));
        float rs = rsqrtf(var + LN_EPS);
        a0 = lrelu(fmaf((a0-m)*rs, G3[lane],    BE3[lane]));
        a1 = lrelu(fmaf((a1-m)*rs, G3[lane+32], BE3[lane+32]));
        a2 = lrelu(fmaf((a2-m)*rs, G3[lane+64], BE3[lane+64]));
        a3 = lrelu(fmaf((a3-m)*rs, G3[lane+96], BE3[lane+96]));
        __syncwarp();
        xb[lane] = a0; xb[lane+32] = a1; xb[lane+64] = a2; xb[lane+96] = a3;
        __syncwarp();

        float c0v = B4[lane], c1v = B4[lane+32];
        #pragma unroll 4
        for (int k = 0; k < 128; k++) {
            float xk = xb[k];
            c0v = fmaf(xk, W4[k*64 + lane],      c0v);
            c1v = fmaf(xk, W4[k*64 + lane + 32], c1v);
        }
        s = c0v + c1v;
        q = c0v*c0v + c1v*c1v;
        #pragma unroll
        for (int d = 16; d; d >>= 1) {
            s += __shfl_xor_sync(0xFFFFFFFFu, s, d);
            q += __shfl_xor_sync(0xFFFFFFFFu, q, d);
        }
        m = s * (1.0f/64.0f);
        var = fmaf(-m, m, q * (1.0f/64.0f));
        rs = rsqrtf(var + LN_EPS);
        c0v = lrelu(fmaf((c0v-m)*rs, G4[lane],    BE4[lane]));
        c1v = lrelu(fmaf((c1v-m)*rs, G4[lane+32], BE4[lane+32]));

        float p = c0v * W5[lane] + c1v * W5[lane+32];
        #pragma unroll
        for (int d = 16; d; d >>= 1) p += __shfl_xor_sync(0xFFFFFFFFu, p, d);
        if (lane == 0) g_score[row] = p + b5v;
    }
}

// ---------------- kernel D: EMA normalize + tanh ----------------
__global__ void k_final(float* __restrict__ out, int B) {
    __shared__ float red[1024];
    int tid = threadIdx.x;
    float s = 0.f;
    for (int i = tid; i < B; i += 1024) s += fabsf(g_score[i]);
    red[tid] = s;
    __syncthreads();
    #pragma unroll
    for (int d = 512; d; d >>= 1) {
        if (tid < d) red[tid] += red[tid + d];
        __syncthreads();
    }
    float mean  = red[0] / (float)B;
    float ema   = 0.99f + 0.01f * mean;
    float denom = fmaxf(ema, 0.1f);
    for (int i = tid; i < B; i += 1024) {
        float sc = g_score[i] / denom;
        sc = fminf(fmaxf(sc, -5.0f), 5.0f);
        out[i] = 10.0f * tanhf(sc * 0.2f);
    }
}

// ---------------- launch ----------------
extern "C" void kernel_launch(void* const* d_in, const int* in_sizes, int n_in,
                              void* d_out, int out_size) {
    const float* muons = (const float*)d_in[0];
    const int*   bidx  = (const int*)  d_in[1];
    const float* cond  = (const float*)d_in[2];
    const float* w1  = (const float*)d_in[4];
    const float* b1  = (const float*)d_in[5];
    const float* g1  = (const float*)d_in[6];
    const float* be1 = (const float*)d_in[7];
    const float* w2  = (const float*)d_in[8];
    const float* b2  = (const float*)d_in[9];
    const float* g2  = (const float*)d_in[10];
    const float* be2 = (const float*)d_in[11];
    const float* w3  = (const float*)d_in[12];
    const float* b3  = (const float*)d_in[13];
    const float* g3  = (const float*)d_in[14];
    const float* be3 = (const float*)d_in[15];
    const float* w4  = (const float*)d_in[16];
    const float* b4  = (const float*)d_in[17];
    const float* g4  = (const float*)d_in[18];
    const float* be4 = (const float*)d_in[19];
    const float* w5  = (const float*)d_in[20];
    const float* b5  = (const float*)d_in[21];

    int N = in_sizes[0] / 3;
    int B = in_sizes[2] / 4;
    if (B > MAXB) B = MAXB;

    static const size_t SMEM_DEC = (size_t)(16896 + 8192 + 64 + 128*3 + 64*3 + 8*136) * 4;
    cudaFuncSetAttribute(k_main, cudaFuncAttributeMaxDynamicSharedMemorySize, (int)SMEM_NEED);
    cudaFuncSetAttribute(k_dec,  cudaFuncAttributeMaxDynamicSharedMemorySize, (int)SMEM_DEC);

    int initN = B * 128;
    k_init<<<(initN + 255) / 256, 256>>>(initN);

    int nTiles = (N + ROWS - 1) / ROWS;
    int nBlocks = 2 * 148;
    if (nBlocks > nTiles) nBlocks = nTiles;
    k_main<<<nBlocks, TB, SMEM_NEED>>>(muons, bidx, cond,
                                       w1, b1, g1, be1, w2, b2, g2, be2, N, nTiles);

    int decBlocks = (B + 31) / 32;
    k_dec<<<decBlocks, 256, SMEM_DEC>>>(cond, w3, b3, g3, be3,
                                        w4, b4, g4, be4, w5, b5, B);

    k_final<<<1, 1024>>>((float*)d_out, B);
}

// round 5
// speedup vs baseline: 1.7086x; 1.0787x over previous
#include <cuda_runtime.h>
#include <math.h>
#include <cstdint>

#define LN_EPS 1e-5f
#define NEG_FILL -1.0e9f
#define MAXB 8192

// ---------------- device scratch ----------------
__device__ unsigned g_gf_enc[MAXB * 128];
__device__ float    g_score[MAXB];

// ---------------- helpers ----------------
__device__ __forceinline__ unsigned enc_f(float f) {
    int i = __float_as_int(f);
    unsigned u = (unsigned)i;
    return (i < 0) ? ~u : (u | 0x80000000u);
}
__device__ __forceinline__ float dec_f(unsigned u) {
    return (u & 0x80000000u) ? __int_as_float((int)(u & 0x7FFFFFFFu))
                             : __int_as_float((int)(~u));
}
__device__ __forceinline__ float lrelu(float v) { return v >= 0.0f ? v : 0.2f * v; }
__device__ __forceinline__ uint32_t f2tf32(float f) {
    uint32_t u;
    asm("cvt.rna.tf32.f32 %0, %1;" : "=r"(u) : "f"(f));
    return u;
}
__device__ __forceinline__ uint32_t smem_u32(const void* p) {
    return (uint32_t)__cvta_generic_to_shared(p);
}
__device__ __forceinline__ void cp_async16(uint32_t dst, const void* src, bool full) {
    int sz = full ? 16 : 0;
    asm volatile("cp.async.cg.shared.global [%0], [%1], 16, %2;"
                 :: "r"(dst), "l"(src), "r"(sz));
}
#define CP_COMMIT() asm volatile("cp.async.commit_group;" ::: "memory")
#define CP_WAIT0()  asm volatile("cp.async.wait_group 0;" ::: "memory")

// tf32 warp MMA: D(16x8) += A(16x8) * B(8x8)
__device__ __forceinline__ void mma_tf32(float& c0, float& c1, float& c2, float& c3,
                                         uint32_t a0, uint32_t a1, uint32_t a2, uint32_t a3,
                                         uint32_t b0, uint32_t b1) {
    asm volatile(
        "mma.sync.aligned.m16n8k8.row.col.f32.tf32.tf32.f32 "
        "{%0,%1,%2,%3}, {%4,%5,%6,%7}, {%8,%9}, {%0,%1,%2,%3};"
        : "+f"(c0), "+f"(c1), "+f"(c2), "+f"(c3)
        : "r"(a0), "r"(a1), "r"(a2), "r"(a3), "r"(b0), "r"(b1));
}

// ---------------- kernel A: init pooled buffer ----------------
__global__ void k_init(int n) {
    int i = blockIdx.x * blockDim.x + threadIdx.x;
    if (i < n) g_gf_enc[i] = enc_f(NEG_FILL);
}

// ---------------- k_main layout ----------------
#define TB 256
#define ROWS 128
#define A_PITCH 76
#define B_PITCH 68
#define SV_PITCH 130
#define OFF_B    66560                 // SVAL 128*130*4 = 66560 (A 38912 aliases low part)
#define OFF_PARM (66560 + 34816)       // B: 128*68*4 = 34816
// params (floats): B2s 128 | G2s 128 | BE2s 128 | SBI 2*128 | Xs 2*384 | Cs 2*512
#define SMEM_NEED (OFF_PARM + 2432 * 4)

__global__ __launch_bounds__(256, 2) void k_main(
    const float* __restrict__ muons, const int* __restrict__ bidx,
    const float* __restrict__ cond,
    const float* __restrict__ w1, const float* __restrict__ b1,
    const float* __restrict__ g1, const float* __restrict__ be1,
    const float* __restrict__ w2, const float* __restrict__ b2,
    const float* __restrict__ g2, const float* __restrict__ be2,
    int N, int nTiles)
{
    extern __shared__ char base[];
    uint32_t* const Au   = (uint32_t*)(base);           // A operand (tf32), k-permuted
    float*    const SVAL = (float*)(base);              // reused post-MMA
    uint32_t* const Bu   = (uint32_t*)(base + OFF_B);   // B operand (tf32), k-permuted
    float*    const PR   = (float*)(base + OFF_PARM);
    float* const B2s  = PR;            // 128
    float* const G2s  = B2s + 128;     // 128
    float* const BE2s = G2s + 128;     // 128
    int*   const SBIb = (int*)(BE2s + 128);  // 2*128
    float* const Xsb  = (float*)(SBIb + 256); // 2*384
    float* const Csb  = Xsb + 768;            // 2*512

    const int tid  = threadIdx.x;
    const int lane = tid & 31;
    const int wrp  = tid >> 5;
    const int quad = lane >> 2;
    const int tig  = lane & 3;
    // permuted storage index for k = lane (and +32 is sidx+32)
    const int sidx = ((lane >> 3) << 3) + ((lane & 3) << 1) + ((lane >> 2) & 1);

    // ---- per-lane constant layer1 params in registers ----
    float w1a[7], w1b[7];
    #pragma unroll
    for (int j = 0; j < 7; j++) { w1a[j] = w1[j*64 + lane]; w1b[j] = w1[j*64 + lane + 32]; }
    const float b1a = b1[lane], b1b = b1[lane + 32];
    const float g1a = g1[lane], g1b = g1[lane + 32];
    const float e1a = be1[lane], e1b = be1[lane + 32];

    // ---- one-time smem: layer2 params + B operand (k-permuted) ----
    for (int i = tid; i < 128; i += TB) { B2s[i] = b2[i]; G2s[i] = g2[i]; BE2s[i] = be2[i]; }
    for (int i = tid; i < 8192; i += TB) {
        int n = i & 127, k = i >> 7;
        int sk = ((k >> 3) << 3) + ((k & 3) << 1) + ((k >> 2) & 1);
        Bu[n * B_PITCH + sk] = f2tf32(w2[k * 128 + n]);
    }

    // ---- prologue: synchronous stage-0 for first tile into buffer 0 ----
    {
        int rbase = blockIdx.x * ROWS;
        if (tid < 128) {
            int r = rbase + tid;
            int bi = (r < N) ? bidx[r] : -1;
            SBIb[tid] = bi;
            float4 c4 = (bi >= 0) ? *(const float4*)(cond + 4 * bi)
                                  : make_float4(0.f, 0.f, 0.f, 0.f);
            *(float4*)(Csb + tid * 4) = c4;
        }
        for (int i = tid; i < 384; i += TB) {
            int gi = rbase * 3 + i;
            Xsb[i] = (gi < 3 * N) ? muons[gi] : 0.f;
        }
    }
    __syncthreads();

    const uint32_t xs_base  = smem_u32(Xsb);
    const uint32_t sbi_base = smem_u32(SBIb);

    int it = 0;
    for (int tile = blockIdx.x; tile < nTiles; tile += gridDim.x, it ^= 1) {
        const int   bufc = it, bufn = it ^ 1;
        const float* Xc = Xsb + bufc * 384;
        const float* Cc = Csb + bufc * 512;
        const int*   SBc = SBIb + bufc * 128;
        int*         SBn = SBIb + bufn * 128;
        float*       Cn  = Csb + bufn * 512;

        const int  tnxt   = tile + gridDim.x;
        const bool vn     = tnxt < nTiles;
        const int  rbase2 = tnxt * ROWS;

        // ---- prefetch next tile's muons + batch_index ----
        if (vn) {
            if (tid < 96) {
                int gi = rbase2 * 3 + tid * 4;
                cp_async16(xs_base + (bufn * 384 + tid * 4) * 4, muons + gi, gi + 4 <= 3 * N);
            } else if (tid < 128) {
                int t2 = tid - 96;
                int gi = rbase2 + t2 * 4;
                cp_async16(sbi_base + (bufn * 128 + t2 * 4) * 4, bidx + gi, gi + 4 <= N);
            }
        }
        CP_COMMIT();

        // ---- stage 1: layer1 (7->64) + LN(64) + lrelu -> A (tf32, k-permuted) ----
        #pragma unroll 4
        for (int i = 0; i < 16; i++) {
            int lr = wrp * 16 + i;
            float x0 = Xc[lr*3], x1 = Xc[lr*3+1], x2 = Xc[lr*3+2];
            float4 cc = *(const float4*)(Cc + lr * 4);
            float oa = b1a, ob = b1b;
            oa = fmaf(x0,   w1a[0], oa);  ob = fmaf(x0,   w1b[0], ob);
            oa = fmaf(x1,   w1a[1], oa);  ob = fmaf(x1,   w1b[1], ob);
            oa = fmaf(x2,   w1a[2], oa);  ob = fmaf(x2,   w1b[2], ob);
            oa = fmaf(cc.x, w1a[3], oa);  ob = fmaf(cc.x, w1b[3], ob);
            oa = fmaf(cc.y, w1a[4], oa);  ob = fmaf(cc.y, w1b[4], ob);
            oa = fmaf(cc.z, w1a[5], oa);  ob = fmaf(cc.z, w1b[5], ob);
            oa = fmaf(cc.w, w1a[6], oa);  ob = fmaf(cc.w, w1b[6], ob);
            float s = oa + ob, q = oa*oa + ob*ob;
            #pragma unroll
            for (int d = 16; d; d >>= 1) {
                s += __shfl_xor_sync(0xFFFFFFFFu, s, d);
                q += __shfl_xor_sync(0xFFFFFFFFu, q, d);
            }
            float m    = s * (1.0f/64.0f);
            float var  = fmaf(-m, m, q * (1.0f/64.0f));
            float rstd = rsqrtf(var + LN_EPS);
            float ha = lrelu(fmaf((oa - m) * rstd, g1a, e1a));
            float hb = lrelu(fmaf((ob - m) * rstd, g1b, e1b));
            Au[lr * A_PITCH + sidx]      = f2tf32(ha);
            Au[lr * A_PITCH + sidx + 32] = f2tf32(hb);
        }
        __syncwarp();   // stage-2 A reads are warp-local

        // ---- stage 2: GEMM 16x128x64 per warp, LDS.64 operands ----
        float acc[16][4];
        #pragma unroll
        for (int nt = 0; nt < 16; nt++)
            #pragma unroll
            for (int c = 0; c < 4; c++) acc[nt][c] = 0.f;

        const uint32_t* ap0 = Au + (wrp * 16 + quad) * A_PITCH + tig * 2;
        const uint32_t* ap1 = ap0 + 8 * A_PITCH;
        const uint32_t* bp  = Bu + quad * B_PITCH + tig * 2;
        #pragma unroll
        for (int ks = 0; ks < 8; ks++) {
            uint2 A0 = *(const uint2*)(ap0 + ks * 8);
            uint2 A1 = *(const uint2*)(ap1 + ks * 8);
            #pragma unroll
            for (int nt = 0; nt < 16; nt++) {
                uint2 Bv = *(const uint2*)(bp + nt * 8 * B_PITCH + ks * 8);
                mma_tf32(acc[nt][0], acc[nt][1], acc[nt][2], acc[nt][3],
                         A0.x, A1.x, A0.y, A1.y, Bv.x, Bv.y);
            }
        }
        CP_WAIT0();
        __syncthreads();   // A fully read; prefetch visible to all

        // ---- gather next tile's conditions (LDG in flight during stage 3a/3b) ----
        float4 c4n = make_float4(0.f, 0.f, 0.f, 0.f);
        if (vn && tid < 128) {
            int r2 = rbase2 + tid;
            int bi;
            if (rbase2 + ROWS > N) { bi = (r2 < N) ? bidx[r2] : -1; SBn[tid] = bi; }
            else bi = SBn[tid];
            if (vn && rbase2 + ROWS > N) {
                // rare tail: also re-fill Xs scalars (cp.async zfilled partial chunks)
            }
            if (bi >= 0) c4n = *(const float4*)(cond + 4 * bi);
        }
        if (vn && rbase2 + ROWS > N) {
            for (int i = tid; i < 384; i += TB) {
                int gi = rbase2 * 3 + i;
                Xsb[bufn * 384 + i] = (gi < 3 * N) ? muons[gi] : 0.f;
            }
        }

        // ---- stage 3a: bias + LN(128) stats (quad-local) ----
        float sA = 0.f, qA = 0.f, sB = 0.f, qB = 0.f;
        #pragma unroll
        for (int nt = 0; nt < 16; nt++) {
            int col = nt * 8 + tig * 2;
            float2 bb = *(const float2*)(B2s + col);
            acc[nt][0] += bb.x; acc[nt][1] += bb.y;
            acc[nt][2] += bb.x; acc[nt][3] += bb.y;
            sA += acc[nt][0] + acc[nt][1];
            qA = fmaf(acc[nt][0], acc[nt][0], fmaf(acc[nt][1], acc[nt][1], qA));
            sB += acc[nt][2] + acc[nt][3];
            qB = fmaf(acc[nt][2], acc[nt][2], fmaf(acc[nt][3], acc[nt][3], qB));
        }
        #pragma unroll
        for (int d = 1; d <= 2; d <<= 1) {
            sA += __shfl_xor_sync(0xFFFFFFFFu, sA, d);
            qA += __shfl_xor_sync(0xFFFFFFFFu, qA, d);
            sB += __shfl_xor_sync(0xFFFFFFFFu, sB, d);
            qB += __shfl_xor_sync(0xFFFFFFFFu, qB, d);
        }
        float mA  = sA * (1.0f/128.0f);
        float rsA = rsqrtf(fmaf(-mA, mA, qA * (1.0f/128.0f)) + LN_EPS);
        float mB  = sB * (1.0f/128.0f);
        float rsB = rsqrtf(fmaf(-mB, mB, qB * (1.0f/128.0f)) + LN_EPS);

        // ---- stage 3b: normalize + lrelu + nan guard -> SVAL (STS.64) ----
        const int ra = wrp * 16 + quad;
        const int rb = ra + 8;
        #pragma unroll
        for (int nt = 0; nt < 16; nt++) {
            int col = nt * 8 + tig * 2;
            float2 gg = *(const float2*)(G2s + col);
            float2 ee = *(const float2*)(BE2s + col);
            float v0 = lrelu(fmaf((acc[nt][0] - mA) * rsA, gg.x, ee.x));
            float v1 = lrelu(fmaf((acc[nt][1] - mA) * rsA, gg.y, ee.y));
            float v2 = lrelu(fmaf((acc[nt][2] - mB) * rsB, gg.x, ee.x));
            float v3 = lrelu(fmaf((acc[nt][3] - mB) * rsB, gg.y, ee.y));
            if (!isfinite(v0)) v0 = 0.f;
            if (!isfinite(v1)) v1 = 0.f;
            if (!isfinite(v2)) v2 = 0.f;
            if (!isfinite(v3)) v3 = 0.f;
            *(float2*)(SVAL + ra * SV_PITCH + col) = make_float2(v0, v1);
            *(float2*)(SVAL + rb * SV_PITCH + col) = make_float2(v2, v3);
        }
        if (vn && tid < 128) *(float4*)(Cn + tid * 4) = c4n;
        __syncthreads();

        // ---- stage 3c: run-length segment max (sorted batch_index) ----
        {
            int c  = tid & 127;
            int r0 = (tid >> 7) * 64;
            float cur = -3.0e38f;
            int curbi = SBc[r0];
            #pragma unroll 1
            for (int rr = 0; rr < 64; rr++) {
                int lrow = r0 + rr;
                int bi = SBc[lrow];
                float v = SVAL[lrow * SV_PITCH + c];
                if (bi != curbi) {
                    if (curbi >= 0) atomicMax(&g_gf_enc[curbi * 128 + c], enc_f(cur));
                    curbi = bi; cur = v;
                } else {
                    cur = fmaxf(cur, v);
                }
            }
            if (curbi >= 0) atomicMax(&g_gf_enc[curbi * 128 + c], enc_f(cur));
        }
        __syncthreads();   // SVAL/A + buffers reuse barrier
    }
}

// ---------------- kernel C: decision net ----------------
__global__ __launch_bounds__(256) void k_dec(
    const float* __restrict__ cond,
    const float* __restrict__ w3, const float* __restrict__ b3,
    const float* __restrict__ g3, const float* __restrict__ be3,
    const float* __restrict__ w4, const float* __restrict__ b4,
    const float* __restrict__ g4, const float* __restrict__ be4,
    const float* __restrict__ w5, const float* __restrict__ b5,
    int B)
{
    extern __shared__ float sm[];
    float* W3 = sm;
    float* W4 = W3 + 16896;
    float* W5 = W4 + 8192;
    float* B3 = W5 + 64;
    float* G3 = B3 + 128;
    float* BE3= G3 + 128;
    float* B4 = BE3 + 128;
    float* G4 = B4 + 64;
    float* BE4= G4 + 64;
    float* XB = BE4 + 64;

    const int tid = threadIdx.x, lane = tid & 31, wrp = tid >> 5;
    for (int i = tid; i < 16896; i += 256) W3[i] = w3[i];
    for (int i = tid; i < 8192;  i += 256) W4[i] = w4[i];
    for (int i = tid; i < 64;    i += 256) { W5[i] = w5[i]; B4[i] = b4[i]; G4[i] = g4[i]; BE4[i] = be4[i]; }
    for (int i = tid; i < 128;   i += 256) { B3[i] = b3[i]; G3[i] = g3[i]; BE3[i] = be3[i]; }
    __syncthreads();

    float* xb = XB + wrp * 136;
    const float b5v = b5[0];

    #pragma unroll 1
    for (int i = 0; i < 4; i++) {
        int row = (blockIdx.x * 8 + wrp) * 4 + i;
        if (row >= B) break;
        __syncwarp();
        #pragma unroll
        for (int j = 0; j < 4; j++) {
            float v = dec_f(g_gf_enc[row*128 + lane + 32*j]);
            if (isnan(v)) v = NEG_FILL;
            else if (isinf(v)) v = (v > 0.f) ? 1.0e9f : NEG_FILL;
            xb[lane + 32*j] = v;
        }
        if (lane < 4) xb[128 + lane] = cond[row*4 + lane];
        __syncwarp();

        float a0 = B3[lane], a1 = B3[lane+32], a2 = B3[lane+64], a3 = B3[lane+96];
        #pragma unroll 4
        for (int k = 0; k < 132; k++) {
            float xk = xb[k];
            const float* wr = W3 + k*128;
            a0 = fmaf(xk, wr[lane],      a0);
            a1 = fmaf(xk, wr[lane+32],   a1);
            a2 = fmaf(xk, wr[lane+64],   a2);
            a3 = fmaf(xk, wr[lane+96],   a3);
        }
        float s = a0+a1+a2+a3;
        float q = a0*a0 + a1*a1 + a2*a2 + a3*a3;
        #pragma unroll
        for (int d = 16; d; d >>= 1) {
            s += __shfl_xor_sync(0xFFFFFFFFu, s, d);
            q += __shfl_xor_sync(0xFFFFFFFFu, q, d);
        }
        float m = s * (1.0f/128.0f);
        float var = fmaf(-m, m, q * (1.0f/128.0f));
        float rs = rsqrtf(var + LN_EPS);
        a0 = lrelu(fmaf((a0-m)*rs, G3[lane],    BE3[lane]));
        a1 = lrelu(fmaf((a1-m)*rs, G3[lane+32], BE3[lane+32]));
        a2 = lrelu(fmaf((a2-m)*rs, G3[lane+64], BE3[lane+64]));
        a3 = lrelu(fmaf((a3-m)*rs, G3[lane+96], BE3[lane+96]));
        __syncwarp();
        xb[lane] = a0; xb[lane+32] = a1; xb[lane+64] = a2; xb[lane+96] = a3;
        __syncwarp();

        float c0v = B4[lane], c1v = B4[lane+32];
        #pragma unroll 4
        for (int k = 0; k < 128; k++) {
            float xk = xb[k];
            c0v = fmaf(xk, W4[k*64 + lane],      c0v);
            c1v = fmaf(xk, W4[k*64 + lane + 32], c1v);
        }
        s = c0v + c1v;
        q = c0v*c0v + c1v*c1v;
        #pragma unroll
        for (int d = 16; d; d >>= 1) {
            s += __shfl_xor_sync(0xFFFFFFFFu, s, d);
            q += __shfl_xor_sync(0xFFFFFFFFu, q, d);
        }
        m = s * (1.0f/64.0f);
        var = fmaf(-m, m, q * (1.0f/64.0f));
        rs = rsqrtf(var + LN_EPS);
        c0v = lrelu(fmaf((c0v-m)*rs, G4[lane],    BE4[lane]));
        c1v = lrelu(fmaf((c1v-m)*rs, G4[lane+32], BE4[lane+32]));

        float p = c0v * W5[lane] + c1v * W5[lane+32];
        #pragma unroll
        for (int d = 16; d; d >>= 1) p += __shfl_xor_sync(0xFFFFFFFFu, p, d);
        if (lane == 0) g_score[row] = p + b5v;
    }
}

// ---------------- kernel D: EMA normalize + tanh ----------------
__global__ void k_final(float* __restrict__ out, int B) {
    __shared__ float red[1024];
    int tid = threadIdx.x;
    float s = 0.f;
    for (int i = tid; i < B; i += 1024) s += fabsf(g_score[i]);
    red[tid] = s;
    __syncthreads();
    #pragma unroll
    for (int d = 512; d; d >>= 1) {
        if (tid < d) red[tid] += red[tid + d];
        __syncthreads();
    }
    float mean  = red[0] / (float)B;
    float ema   = 0.99f + 0.01f * mean;
    float denom = fmaxf(ema, 0.1f);
    for (int i = tid; i < B; i += 1024) {
        float sc = g_score[i] / denom;
        sc = fminf(fmaxf(sc, -5.0f), 5.0f);
        out[i] = 10.0f * tanhf(sc * 0.2f);
    }
}

// ---------------- launch ----------------
extern "C" void kernel_launch(void* const* d_in, const int* in_sizes, int n_in,
                              void* d_out, int out_size) {
    const float* muons = (const float*)d_in[0];
    const int*   bidx  = (const int*)  d_in[1];
    const float* cond  = (const float*)d_in[2];
    const float* w1  = (const float*)d_in[4];
    const float* b1  = (const float*)d_in[5];
    const float* g1  = (const float*)d_in[6];
    const float* be1 = (const float*)d_in[7];
    const float* w2  = (const float*)d_in[8];
    const float* b2  = (const float*)d_in[9];
    const float* g2  = (const float*)d_in[10];
    const float* be2 = (const float*)d_in[11];
    const float* w3  = (const float*)d_in[12];
    const float* b3  = (const float*)d_in[13];
    const float* g3  = (const float*)d_in[14];
    const float* be3 = (const float*)d_in[15];
    const float* w4  = (const float*)d_in[16];
    const float* b4  = (const float*)d_in[17];
    const float* g4  = (const float*)d_in[18];
    const float* be4 = (const float*)d_in[19];
    const float* w5  = (const float*)d_in[20];
    const float* b5  = (const float*)d_in[21];

    int N = in_sizes[0] / 3;
    int B = in_sizes[2] / 4;
    if (B > MAXB) B = MAXB;

    static const size_t SMEM_DEC = (size_t)(16896 + 8192 + 64 + 128*3 + 64*3 + 8*136) * 4;
    cudaFuncSetAttribute(k_main, cudaFuncAttributeMaxDynamicSharedMemorySize, (int)SMEM_NEED);
    cudaFuncSetAttribute(k_dec,  cudaFuncAttributeMaxDynamicSharedMemorySize, (int)SMEM_DEC);

    int initN = B * 128;
    k_init<<<(initN + 255) / 256, 256>>>(initN);

    int nTiles = (N + ROWS - 1) / ROWS;
    int nBlocks = 2 * 148;
    if (nBlocks > nTiles) nBlocks = nTiles;
    k_main<<<nBlocks, TB, SMEM_NEED>>>(muons, bidx, cond,
                                       w1, b1, g1, be1, w2, b2, g2, be2, N, nTiles);

    int decBlocks = (B + 31) / 32;
    k_dec<<<decBlocks, 256, SMEM_DEC>>>(cond, w3, b3, g3, be3,
                                        w4, b4, g4, be4, w5, b5, B);

    k_final<<<1, 1024>>>((float*)d_out, B);
}

// round 6
// speedup vs baseline: 1.9823x; 1.1602x over previous
#include <cuda_runtime.h>
#include <math.h>
#include <cstdint>

#define LN_EPS 1e-5f
#define NEG_FILL -1.0e9f
#define MAXB 8192

// ---------------- device scratch ----------------
__device__ unsigned g_gf_enc[MAXB * 128];
__device__ float    g_score[MAXB];

// ---------------- helpers ----------------
__device__ __forceinline__ unsigned enc_f(float f) {
    int i = __float_as_int(f);
    unsigned u = (unsigned)i;
    return (i < 0) ? ~u : (u | 0x80000000u);
}
__device__ __forceinline__ float dec_f(unsigned u) {
    return (u & 0x80000000u) ? __int_as_float((int)(u & 0x7FFFFFFFu))
                             : __int_as_float((int)(~u));
}
__device__ __forceinline__ float lrelu(float v) { return v >= 0.0f ? v : 0.2f * v; }
__device__ __forceinline__ uint32_t f2tf32(float f) {
    uint32_t u;
    asm("cvt.rna.tf32.f32 %0, %1;" : "=r"(u) : "f"(f));
    return u;
}
__device__ __forceinline__ uint32_t smem_u32(const void* p) {
    return (uint32_t)__cvta_generic_to_shared(p);
}
__device__ __forceinline__ void cp_async16(uint32_t dst, const void* src, bool full) {
    int sz = full ? 16 : 0;
    asm volatile("cp.async.cg.shared.global [%0], [%1], 16, %2;"
                 :: "r"(dst), "l"(src), "r"(sz));
}
#define CP_COMMIT() asm volatile("cp.async.commit_group;" ::: "memory")
#define CP_WAIT0()  asm volatile("cp.async.wait_group 0;" ::: "memory")

// tf32 warp MMA: D(16x8) += A(16x8) * B(8x8)
__device__ __forceinline__ void mma_tf32(float& c0, float& c1, float& c2, float& c3,
                                         uint32_t a0, uint32_t a1, uint32_t a2, uint32_t a3,
                                         uint32_t b0, uint32_t b1) {
    asm volatile(
        "mma.sync.aligned.m16n8k8.row.col.f32.tf32.tf32.f32 "
        "{%0,%1,%2,%3}, {%4,%5,%6,%7}, {%8,%9}, {%0,%1,%2,%3};"
        : "+f"(c0), "+f"(c1), "+f"(c2), "+f"(c3)
        : "r"(a0), "r"(a1), "r"(a2), "r"(a3), "r"(b0), "r"(b1));
}

// ---------------- kernel A: init pooled buffer ----------------
__global__ void k_init(int n) {
    int i = blockIdx.x * blockDim.x + threadIdx.x;
    if (i < n) g_gf_enc[i] = enc_f(NEG_FILL);
}

// ---------------- k_main layout ----------------
#define TB 256
#define ROWS 128
#define A_PITCH 76           // == 12 mod 32 -> conflict-free LDS.64 fragments
#define B_PITCH 76           // (was 68 == 4 mod 32: 2-way conflicts; fixed)
#define OFF_B    38912                 // A: 128*76*4
#define OFF_PARM (38912 + 38912)       // B: 128*76*4
// params (floats): B2s 128 | G2s 128 | BE2s 128 | SBI 2*128(int) | Xs 2*384 | Cs 2*512 | Ewp 8(int)
#define SMEM_NEED (OFF_PARM + 2440 * 4)

__global__ __launch_bounds__(256, 2) void k_main(
    const float* __restrict__ muons, const int* __restrict__ bidx,
    const float* __restrict__ cond,
    const float* __restrict__ w1, const float* __restrict__ b1,
    const float* __restrict__ g1, const float* __restrict__ be1,
    const float* __restrict__ w2, const float* __restrict__ b2,
    const float* __restrict__ g2, const float* __restrict__ be2,
    int N, int nTiles)
{
    extern __shared__ char base[];
    uint32_t* const Au   = (uint32_t*)(base);           // A operand (tf32), k-permuted
    float*    const Wst  = (float*)(base);              // per-warp col-max staging (aliases A)
    uint32_t* const Bu   = (uint32_t*)(base + OFF_B);   // B operand (tf32), k-permuted
    float*    const PR   = (float*)(base + OFF_PARM);
    float* const B2s  = PR;            // 128
    float* const G2s  = B2s + 128;     // 128
    float* const BE2s = G2s + 128;     // 128
    int*   const SBIb = (int*)(BE2s + 128);   // 2*128
    float* const Xsb  = (float*)(SBIb + 256); // 2*384
    float* const Csb  = Xsb + 768;            // 2*512
    int*   const Ewp  = (int*)(Csb + 1024);   // 8

    const int tid  = threadIdx.x;
    const int lane = tid & 31;
    const int wrp  = tid >> 5;
    const int quad = lane >> 2;
    const int tig  = lane & 3;
    // permuted storage index for k = lane (and +32 is sidx+32)
    const int sidx = ((lane >> 3) << 3) + ((lane & 3) << 1) + ((lane >> 2) & 1);

    // ---- per-lane constant layer1 params in registers ----
    float w1a[7], w1b[7];
    #pragma unroll
    for (int j = 0; j < 7; j++) { w1a[j] = w1[j*64 + lane]; w1b[j] = w1[j*64 + lane + 32]; }
    const float b1a = b1[lane], b1b = b1[lane + 32];
    const float g1a = g1[lane], g1b = g1[lane + 32];
    const float e1a = be1[lane], e1b = be1[lane + 32];

    // ---- one-time smem: layer2 params + B operand (k-permuted) ----
    for (int i = tid; i < 128; i += TB) { B2s[i] = b2[i]; G2s[i] = g2[i]; BE2s[i] = be2[i]; }
    for (int i = tid; i < 8192; i += TB) {
        int n = i & 127, k = i >> 7;
        int sk = ((k >> 3) << 3) + ((k & 3) << 1) + ((k >> 2) & 1);
        Bu[n * B_PITCH + sk] = f2tf32(w2[k * 128 + n]);
    }

    // ---- prologue: synchronous stage-0 for first tile into buffer 0 ----
    {
        int rbase = blockIdx.x * ROWS;
        if (tid < 128) {
            int r = rbase + tid;
            int bi = (r < N) ? bidx[r] : -1;
            SBIb[tid] = bi;
            float4 c4 = (bi >= 0) ? *(const float4*)(cond + 4 * bi)
                                  : make_float4(0.f, 0.f, 0.f, 0.f);
            *(float4*)(Csb + tid * 4) = c4;
        }
        for (int i = tid; i < 384; i += TB) {
            int gi = rbase * 3 + i;
            Xsb[i] = (gi < 3 * N) ? muons[gi] : 0.f;
        }
    }
    __syncthreads();

    const uint32_t xs_base  = smem_u32(Xsb);
    const uint32_t sbi_base = smem_u32(SBIb);

    int it = 0;
    for (int tile = blockIdx.x; tile < nTiles; tile += gridDim.x, it ^= 1) {
        const int   bufc = it, bufn = it ^ 1;
        const float* Xc  = Xsb + bufc * 384;
        const float* Cc  = Csb + bufc * 512;
        const int*   SBc = SBIb + bufc * 128;
        const int*   SBn = SBIb + bufn * 128;
        float*       Cn  = Csb + bufn * 512;

        const int  tnxt   = tile + gridDim.x;
        const bool vn     = tnxt < nTiles;
        const int  rbase2 = tnxt * ROWS;

        // ---- prefetch next tile's muons + batch_index ----
        if (vn) {
            if (tid < 96) {
                int gi = rbase2 * 3 + tid * 4;
                cp_async16(xs_base + (bufn * 384 + tid * 4) * 4, muons + gi, gi + 4 <= 3 * N);
            } else if (tid < 128) {
                int t2 = tid - 96;
                int gi = rbase2 + t2 * 4;
                cp_async16(sbi_base + (bufn * 128 + t2 * 4) * 4, bidx + gi, gi + 4 <= N);
            }
        }
        CP_COMMIT();

        // ---- stage 1: layer1 (7->64) + LN(64) + lrelu -> A (tf32, k-permuted) ----
        #pragma unroll 4
        for (int i = 0; i < 16; i++) {
            int lr = wrp * 16 + i;
            float x0 = Xc[lr*3], x1 = Xc[lr*3+1], x2 = Xc[lr*3+2];
            float4 cc = *(const float4*)(Cc + lr * 4);
            float oa = b1a, ob = b1b;
            oa = fmaf(x0,   w1a[0], oa);  ob = fmaf(x0,   w1b[0], ob);
            oa = fmaf(x1,   w1a[1], oa);  ob = fmaf(x1,   w1b[1], ob);
            oa = fmaf(x2,   w1a[2], oa);  ob = fmaf(x2,   w1b[2], ob);
            oa = fmaf(cc.x, w1a[3], oa);  ob = fmaf(cc.x, w1b[3], ob);
            oa = fmaf(cc.y, w1a[4], oa);  ob = fmaf(cc.y, w1b[4], ob);
            oa = fmaf(cc.z, w1a[5], oa);  ob = fmaf(cc.z, w1b[5], ob);
            oa = fmaf(cc.w, w1a[6], oa);  ob = fmaf(cc.w, w1b[6], ob);
            float s = oa + ob, q = oa*oa + ob*ob;
            #pragma unroll
            for (int d = 16; d; d >>= 1) {
                s += __shfl_xor_sync(0xFFFFFFFFu, s, d);
                q += __shfl_xor_sync(0xFFFFFFFFu, q, d);
            }
            float m    = s * (1.0f/64.0f);
            float var  = fmaf(-m, m, q * (1.0f/64.0f));
            float rstd = rsqrtf(var + LN_EPS);
            float ha = lrelu(fmaf((oa - m) * rstd, g1a, e1a));
            float hb = lrelu(fmaf((ob - m) * rstd, g1b, e1b));
            Au[lr * A_PITCH + sidx]      = f2tf32(ha);
            Au[lr * A_PITCH + sidx + 32] = f2tf32(hb);
        }
        __syncwarp();   // stage-2 A reads are warp-local

        // ---- stage 2: GEMM 16x128x64 per warp, LDS.64 operands ----
        float acc[16][4];
        #pragma unroll
        for (int nt = 0; nt < 16; nt++)
            #pragma unroll
            for (int c = 0; c < 4; c++) acc[nt][c] = 0.f;

        const uint32_t* ap0 = Au + (wrp * 16 + quad) * A_PITCH + tig * 2;
        const uint32_t* ap1 = ap0 + 8 * A_PITCH;
        const uint32_t* bp  = Bu + quad * B_PITCH + tig * 2;
        #pragma unroll
        for (int ks = 0; ks < 8; ks++) {
            uint2 A0 = *(const uint2*)(ap0 + ks * 8);
            uint2 A1 = *(const uint2*)(ap1 + ks * 8);
            #pragma unroll
            for (int nt = 0; nt < 16; nt++) {
                uint2 Bv = *(const uint2*)(bp + nt * 8 * B_PITCH + ks * 8);
                mma_tf32(acc[nt][0], acc[nt][1], acc[nt][2], acc[nt][3],
                         A0.x, A1.x, A0.y, A1.y, Bv.x, Bv.y);
            }
        }

        // ---- stage 3a: bias + LN(128) stats (quad-local, registers) ----
        float sA = 0.f, qA = 0.f, sB = 0.f, qB = 0.f;
        #pragma unroll
        for (int nt = 0; nt < 16; nt++) {
            int col = nt * 8 + tig * 2;
            float2 bb = *(const float2*)(B2s + col);
            acc[nt][0] += bb.x; acc[nt][1] += bb.y;
            acc[nt][2] += bb.x; acc[nt][3] += bb.y;
            sA += acc[nt][0] + acc[nt][1];
            qA = fmaf(acc[nt][0], acc[nt][0], fmaf(acc[nt][1], acc[nt][1], qA));
            sB += acc[nt][2] + acc[nt][3];
            qB = fmaf(acc[nt][2], acc[nt][2], fmaf(acc[nt][3], acc[nt][3], qB));
        }
        #pragma unroll
        for (int d = 1; d <= 2; d <<= 1) {
            sA += __shfl_xor_sync(0xFFFFFFFFu, sA, d);
            qA += __shfl_xor_sync(0xFFFFFFFFu, qA, d);
            sB += __shfl_xor_sync(0xFFFFFFFFu, sB, d);
            qB += __shfl_xor_sync(0xFFFFFFFFu, qB, d);
        }
        float mA  = sA * (1.0f/128.0f);
        float rsA = rsqrtf(fmaf(-mA, mA, qA * (1.0f/128.0f)) + LN_EPS);
        float mB  = sB * (1.0f/128.0f);
        float rsB = rsqrtf(fmaf(-mB, mB, qB * (1.0f/128.0f)) + LN_EPS);

        // ---- stage 3b+3c: normalize + lrelu + nan guard, pool from registers ----
        const int ra = wrp * 16 + quad;
        const int rb = ra + 8;
        const int bi0  = SBc[wrp * 16];
        const int bi15 = SBc[wrp * 16 + 15];
        const bool fast = (bi0 == bi15) && (bi0 >= 0);
        const int bi_ra = SBc[ra];
        const int bi_rb = SBc[rb];
        float* const Wme = Wst + wrp * (16 * A_PITCH);   // warp-private staging (own A rows)

        #pragma unroll
        for (int nt = 0; nt < 16; nt++) {
            int col = nt * 8 + tig * 2;
            float2 gg = *(const float2*)(G2s + col);
            float2 ee = *(const float2*)(BE2s + col);
            float v0 = lrelu(fmaf((acc[nt][0] - mA) * rsA, gg.x, ee.x));
            float v1 = lrelu(fmaf((acc[nt][1] - mA) * rsA, gg.y, ee.y));
            float v2 = lrelu(fmaf((acc[nt][2] - mB) * rsB, gg.x, ee.x));
            float v3 = lrelu(fmaf((acc[nt][3] - mB) * rsB, gg.y, ee.y));
            if (!isfinite(v0)) v0 = 0.f;
            if (!isfinite(v1)) v1 = 0.f;
            if (!isfinite(v2)) v2 = 0.f;
            if (!isfinite(v3)) v3 = 0.f;
            if (fast) {
                // 16-row max via quad butterfly; every lane ends with its 2-col max
                float m0 = fmaxf(v0, v2), m1 = fmaxf(v1, v3);
                #pragma unroll
                for (int d = 4; d <= 16; d <<= 1) {
                    m0 = fmaxf(m0, __shfl_xor_sync(0xFFFFFFFFu, m0, d));
                    m1 = fmaxf(m1, __shfl_xor_sync(0xFFFFFFFFu, m1, d));
                }
                if (quad == 0) *(float2*)(Wme + col) = make_float2(m0, m1);
            } else {
                // rare: boundary inside this warp's 16 rows -> direct flush
                if (bi_ra >= 0) {
                    atomicMax(&g_gf_enc[bi_ra * 128 + col],     enc_f(v0));
                    atomicMax(&g_gf_enc[bi_ra * 128 + col + 1], enc_f(v1));
                }
                if (bi_rb >= 0) {
                    atomicMax(&g_gf_enc[bi_rb * 128 + col],     enc_f(v2));
                    atomicMax(&g_gf_enc[bi_rb * 128 + col + 1], enc_f(v3));
                }
            }
        }
        if (lane == 0) Ewp[wrp] = fast ? bi0 : -1;

        CP_WAIT0();
        __syncthreads();   // Wst/Ewp visible; prefetched buffers visible

        // ---- gather next tile's conditions (loads overlap combine below) ----
        float4 c4n = make_float4(0.f, 0.f, 0.f, 0.f);
        int bin = -1;
        if (vn && tid < 128) {
            if (rbase2 + ROWS > N) bin = (rbase2 + tid < N) ? bidx[rbase2 + tid] : -1;
            else bin = SBn[tid];
            if (bin >= 0) c4n = *(const float4*)(cond + 4 * bin);
        }

        // ---- combine per-warp partials (run-length over 8 warps) ----
        if (tid < 128) {
            int   cure = -1;
            float cur  = -3.0e38f;
            #pragma unroll
            for (int w = 0; w < 8; w++) {
                int e = Ewp[w];
                if (e >= 0) {
                    float v = Wst[w * (16 * A_PITCH) + tid];
                    if (e != cure) {
                        if (cure >= 0) atomicMax(&g_gf_enc[cure * 128 + tid], enc_f(cur));
                        cure = e; cur = v;
                    } else {
                        cur = fmaxf(cur, v);
                    }
                }
            }
            if (cure >= 0) atomicMax(&g_gf_enc[cure * 128 + tid], enc_f(cur));
        }
        if (vn && tid < 128) {
            *(float4*)(Cn + tid * 4) = c4n;
            if (rbase2 + ROWS > N) ((int*)SBn)[tid] = bin;   // tail fixup
        }
        if (vn && rbase2 + ROWS > N) {
            for (int i = tid; i < 384; i += TB) {
                int gi = rbase2 * 3 + i;
                Xsb[bufn * 384 + i] = (gi < 3 * N) ? muons[gi] : 0.f;
            }
        }
        __syncthreads();   // A/Wst + Cn/SBn reuse barrier
    }
}

// ---------------- kernel C: decision net ----------------
__global__ __launch_bounds__(256) void k_dec(
    const float* __restrict__ cond,
    const float* __restrict__ w3, const float* __restrict__ b3,
    const float* __restrict__ g3, const float* __restrict__ be3,
    const float* __restrict__ w4, const float* __restrict__ b4,
    const float* __restrict__ g4, const float* __restrict__ be4,
    const float* __restrict__ w5, const float* __restrict__ b5,
    int B)
{
    extern __shared__ float sm[];
    float* W3 = sm;
    float* W4 = W3 + 16896;
    float* W5 = W4 + 8192;
    float* B3 = W5 + 64;
    float* G3 = B3 + 128;
    float* BE3= G3 + 128;
    float* B4 = BE3 + 128;
    float* G4 = B4 + 64;
    float* BE4= G4 + 64;
    float* XB = BE4 + 64;

    const int tid = threadIdx.x, lane = tid & 31, wrp = tid >> 5;
    for (int i = tid; i < 16896; i += 256) W3[i] = w3[i];
    for (int i = tid; i < 8192;  i += 256) W4[i] = w4[i];
    for (int i = tid; i < 64;    i += 256) { W5[i] = w5[i]; B4[i] = b4[i]; G4[i] = g4[i]; BE4[i] = be4[i]; }
    for (int i = tid; i < 128;   i += 256) { B3[i] = b3[i]; G3[i] = g3[i]; BE3[i] = be3[i]; }
    __syncthreads();

    float* xb = XB + wrp * 136;
    const float b5v = b5[0];

    #pragma unroll 1
    for (int i = 0; i < 4; i++) {
        int row = (blockIdx.x * 8 + wrp) * 4 + i;
        if (row >= B) break;
        __syncwarp();
        #pragma unroll
        for (int j = 0; j < 4; j++) {
            float v = dec_f(g_gf_enc[row*128 + lane + 32*j]);
            if (isnan(v)) v = NEG_FILL;
            else if (isinf(v)) v = (v > 0.f) ? 1.0e9f : NEG_FILL;
            xb[lane + 32*j] = v;
        }
        if (lane < 4) xb[128 + lane] = cond[row*4 + lane];
        __syncwarp();

        float a0 = B3[lane], a1 = B3[lane+32], a2 = B3[lane+64], a3 = B3[lane+96];
        #pragma unroll 4
        for (int k = 0; k < 132; k++) {
            float xk = xb[k];
            const float* wr = W3 + k*128;
            a0 = fmaf(xk, wr[lane],      a0);
            a1 = fmaf(xk, wr[lane+32],   a1);
            a2 = fmaf(xk, wr[lane+64],   a2);
            a3 = fmaf(xk, wr[lane+96],   a3);
        }
        float s = a0+a1+a2+a3;
        float q = a0*a0 + a1*a1 + a2*a2 + a3*a3;
        #pragma unroll
        for (int d = 16; d; d >>= 1) {
            s += __shfl_xor_sync(0xFFFFFFFFu, s, d);
            q += __shfl_xor_sync(0xFFFFFFFFu, q, d);
        }
        float m = s * (1.0f/128.0f);
        float var = fmaf(-m, m, q * (1.0f/128.0f));
        float rs = rsqrtf(var + LN_EPS);
        a0 = lrelu(fmaf((a0-m)*rs, G3[lane],    BE3[lane]));
        a1 = lrelu(fmaf((a1-m)*rs, G3[lane+32], BE3[lane+32]));
        a2 = lrelu(fmaf((a2-m)*rs, G3[lane+64], BE3[lane+64]));
        a3 = lrelu(fmaf((a3-m)*rs, G3[lane+96], BE3[lane+96]));
        __syncwarp();
        xb[lane] = a0; xb[lane+32] = a1; xb[lane+64] = a2; xb[lane+96] = a3;
        __syncwarp();

        float c0v = B4[lane], c1v = B4[lane+32];
        #pragma unroll 4
        for (int k = 0; k < 128; k++) {
            float xk = xb[k];
            c0v = fmaf(xk, W4[k*64 + lane],      c0v);
            c1v = fmaf(xk, W4[k*64 + lane + 32], c1v);
        }
        s = c0v + c1v;
        q = c0v*c0v + c1v*c1v;
        #pragma unroll
        for (int d = 16; d; d >>= 1) {
            s += __shfl_xor_sync(0xFFFFFFFFu, s, d);
            q += __shfl_xor_sync(0xFFFFFFFFu, q, d);
        }
        m = s * (1.0f/64.0f);
        var = fmaf(-m, m, q * (1.0f/64.0f));
        rs = rsqrtf(var + LN_EPS);
        c0v = lrelu(fmaf((c0v-m)*rs, G4[lane],    BE4[lane]));
        c1v = lrelu(fmaf((c1v-m)*rs, G4[lane+32], BE4[lane+32]));

        float p = c0v * W5[lane] + c1v * W5[lane+32];
        #pragma unroll
        for (int d = 16; d; d >>= 1) p += __shfl_xor_sync(0xFFFFFFFFu, p, d);
        if (lane == 0) g_score[row] = p + b5v;
    }
}

// ---------------- kernel D: EMA normalize + tanh ----------------
__global__ void k_final(float* __restrict__ out, int B) {
    __shared__ float red[1024];
    int tid = threadIdx.x;
    float s = 0.f;
    for (int i = tid; i < B; i += 1024) s += fabsf(g_score[i]);
    red[tid] = s;
    __syncthreads();
    #pragma unroll
    for (int d = 512; d; d >>= 1) {
        if (tid < d) red[tid] += red[tid + d];
        __syncthreads();
    }
    float mean  = red[0] / (float)B;
    float ema   = 0.99f + 0.01f * mean;
    float denom = fmaxf(ema, 0.1f);
    for (int i = tid; i < B; i += 1024) {
        float sc = g_score[i] / denom;
        sc = fminf(fmaxf(sc, -5.0f), 5.0f);
        out[i] = 10.0f * tanhf(sc * 0.2f);
    }
}

// ---------------- launch ----------------
extern "C" void kernel_launch(void* const* d_in, const int* in_sizes, int n_in,
                              void* d_out, int out_size) {
    const float* muons = (const float*)d_in[0];
    const int*   bidx  = (const int*)  d_in[1];
    const float* cond  = (const float*)d_in[2];
    const float* w1  = (const float*)d_in[4];
    const float* b1  = (const float*)d_in[5];
    const float* g1  = (const float*)d_in[6];
    const float* be1 = (const float*)d_in[7];
    const float* w2  = (const float*)d_in[8];
    const float* b2  = (const float*)d_in[9];
    const float* g2  = (const float*)d_in[10];
    const float* be2 = (const float*)d_in[11];
    const float* w3  = (const float*)d_in[12];
    const float* b3  = (const float*)d_in[13];
    const float* g3  = (const float*)d_in[14];
    const float* be3 = (const float*)d_in[15];
    const float* w4  = (const float*)d_in[16];
    const float* b4  = (const float*)d_in[17];
    const float* g4  = (const float*)d_in[18];
    const float* be4 = (const float*)d_in[19];
    const float* w5  = (const float*)d_in[20];
    const float* b5  = (const float*)d_in[21];

    int N = in_sizes[0] / 3;
    int B = in_sizes[2] / 4;
    if (B > MAXB) B = MAXB;

    static const size_t SMEM_DEC = (size_t)(16896 + 8192 + 64 + 128*3 + 64*3 + 8*136) * 4;
    cudaFuncSetAttribute(k_main, cudaFuncAttributeMaxDynamicSharedMemorySize, (int)SMEM_NEED);
    cudaFuncSetAttribute(k_dec,  cudaFuncAttributeMaxDynamicSharedMemorySize, (int)SMEM_DEC);

    int initN = B * 128;
    k_init<<<(initN + 255) / 256, 256>>>(initN);

    int nTiles = (N + ROWS - 1) / ROWS;
    int nBlocks = 2 * 148;
    if (nBlocks > nTiles) nBlocks = nTiles;
    k_main<<<nBlocks, TB, SMEM_NEED>>>(muons, bidx, cond,
                                       w1, b1, g1, be1, w2, b2, g2, be2, N, nTiles);

    int decBlocks = (B + 31) / 32;
    k_dec<<<decBlocks, 256, SMEM_DEC>>>(cond, w3, b3, g3, be3,
                                        w4, b4, g4, be4, w5, b5, B);

    k_final<<<1, 1024>>>((float*)d_out, B);
}

// round 7
// speedup vs baseline: 2.0649x; 1.0417x over previous
#include <cuda_runtime.h>
#include <math.h>
#include <cstdint>

#define LN_EPS 1e-5f
#define NEG_FILL -1.0e9f
#define MAXB 8192

// ---------------- device scratch ----------------
__device__ unsigned g_gf_enc[MAXB * 128];
__device__ float    g_score[MAXB];
__device__ float    g_ln1[44];   // closed-form LN(64) coefficients

// ---------------- helpers ----------------
__device__ __forceinline__ unsigned enc_f(float f) {
    int i = __float_as_int(f);
    unsigned u = (unsigned)i;
    return (i < 0) ? ~u : (u | 0x80000000u);
}
__device__ __forceinline__ float dec_f(unsigned u) {
    return (u & 0x80000000u) ? __int_as_float((int)(u & 0x7FFFFFFFu))
                             : __int_as_float((int)(~u));
}
__device__ __forceinline__ float lrelu(float v) { return v >= 0.0f ? v : 0.2f * v; }
__device__ __forceinline__ uint32_t f2tf32(float f) {
    uint32_t u;
    asm("cvt.rna.tf32.f32 %0, %1;" : "=r"(u) : "f"(f));
    return u;
}
__device__ __forceinline__ uint32_t smem_u32(const void* p) {
    return (uint32_t)__cvta_generic_to_shared(p);
}
__device__ __forceinline__ void cp_async16(uint32_t dst, const void* src, bool full) {
    int sz = full ? 16 : 0;
    asm volatile("cp.async.cg.shared.global [%0], [%1], 16, %2;"
                 :: "r"(dst), "l"(src), "r"(sz));
}
#define CP_COMMIT() asm volatile("cp.async.commit_group;" ::: "memory")
#define CP_WAIT0()  asm volatile("cp.async.wait_group 0;" ::: "memory")

// tf32 warp MMA: D(16x8) += A(16x8) * B(8x8)
__device__ __forceinline__ void mma_tf32(float& c0, float& c1, float& c2, float& c3,
                                         uint32_t a0, uint32_t a1, uint32_t a2, uint32_t a3,
                                         uint32_t b0, uint32_t b1) {
    asm volatile(
        "mma.sync.aligned.m16n8k8.row.col.f32.tf32.tf32.f32 "
        "{%0,%1,%2,%3}, {%4,%5,%6,%7}, {%8,%9}, {%0,%1,%2,%3};"
        : "+f"(c0), "+f"(c1), "+f"(c2), "+f"(c3)
        : "r"(a0), "r"(a1), "r"(a2), "r"(a3), "r"(b0), "r"(b1));
}

// ---------------- kernel A: init pooled buffer + LN coefficients ----------------
// LN coeff layout (idx(j,k)=off(j)+(k-j), off={0,7,13,18,22,25,27}):
//  [0..27]  qc   : (j==k?1:2)*G_jk,  G = sum_i w_i w_i^T
//  [28..34] twod : 2 * sum_i b_i W1[j][i]
//  [35..41] mw   : (1/64) sum_i W1[j][i]
//  [42]     mb   : (1/64) sum_i b_i
//  [43]     S0   : sum_i b_i^2
__global__ void k_init(int n, const float* __restrict__ w1, const float* __restrict__ b1) {
    int i = blockIdx.x * blockDim.x + threadIdx.x;
    if (i < n) g_gf_enc[i] = enc_f(NEG_FILL);
    if (blockIdx.x == 0 && threadIdx.x < 44) {
        int t = threadIdx.x;
        float v = 0.f;
        if (t < 28) {
            int j = 0, k = 0, idx = t;
            #pragma unroll 1
            for (j = 0; j < 7; j++) { int len = 7 - j; if (idx < len) { k = j + idx; break; } idx -= len; }
            float s = 0.f;
            for (int e = 0; e < 64; e++) s = fmaf(w1[j*64+e], w1[k*64+e], s);
            v = (j == k) ? s : 2.0f * s;
        } else if (t < 35) {
            int j = t - 28;
            float s = 0.f;
            for (int e = 0; e < 64; e++) s = fmaf(b1[e], w1[j*64+e], s);
            v = 2.0f * s;
        } else if (t < 42) {
            int j = t - 35;
            float s = 0.f;
            for (int e = 0; e < 64; e++) s += w1[j*64+e];
            v = s * (1.0f/64.0f);
        } else if (t == 42) {
            float s = 0.f;
            for (int e = 0; e < 64; e++) s += b1[e];
            v = s * (1.0f/64.0f);
        } else {
            float s = 0.f;
            for (int e = 0; e < 64; e++) s = fmaf(b1[e], b1[e], s);
            v = s;
        }
        g_ln1[t] = v;
    }
}

// ---------------- k_main layout ----------------
#define TB 256
#define ROWS 128
#define A_PITCH 76           // == 12 mod 32 -> conflict-free LDS.64 fragments
#define B_PITCH 76
#define OFF_B    38912                 // A: 128*76*4
#define OFF_PARM (38912 + 38912)       // B: 128*76*4
// params (floats): B2s 128 | G2s 128 | BE2s 128 | SBI 2*128(int) | Xs 2*384 | Cs 2*512 | Ewp 8(int) | LNC 44
#define SMEM_NEED (OFF_PARM + 2484 * 4)

__global__ __launch_bounds__(256, 2) void k_main(
    const float* __restrict__ muons, const int* __restrict__ bidx,
    const float* __restrict__ cond,
    const float* __restrict__ w1, const float* __restrict__ b1,
    const float* __restrict__ g1, const float* __restrict__ be1,
    const float* __restrict__ w2, const float* __restrict__ b2,
    const float* __restrict__ g2, const float* __restrict__ be2,
    int N, int nTiles)
{
    extern __shared__ char base[];
    uint32_t* const Au   = (uint32_t*)(base);           // A operand (tf32), k-permuted
    float*    const Wst  = (float*)(base);              // per-warp col-max staging (aliases A)
    uint32_t* const Bu   = (uint32_t*)(base + OFF_B);   // B operand (tf32), k-permuted
    float*    const PR   = (float*)(base + OFF_PARM);
    float* const B2s  = PR;            // 128
    float* const G2s  = B2s + 128;     // 128
    float* const BE2s = G2s + 128;     // 128
    int*   const SBIb = (int*)(BE2s + 128);   // 2*128
    float* const Xsb  = (float*)(SBIb + 256); // 2*384
    float* const Csb  = Xsb + 768;            // 2*512
    int*   const Ewp  = (int*)(Csb + 1024);   // 8
    float* const LNC  = (float*)(Ewp + 8);    // 44

    const int tid  = threadIdx.x;
    const int lane = tid & 31;
    const int wrp  = tid >> 5;
    const int quad = lane >> 2;
    const int tig  = lane & 3;
    // permuted storage index for k = lane (and +32 is sidx+32)
    const int sidx = ((lane >> 3) << 3) + ((lane & 3) << 1) + ((lane >> 2) & 1);

    // ---- per-lane constant layer1 params in registers ----
    float w1a[7], w1b[7];
    #pragma unroll
    for (int j = 0; j < 7; j++) { w1a[j] = w1[j*64 + lane]; w1b[j] = w1[j*64 + lane + 32]; }
    const float b1a = b1[lane], b1b = b1[lane + 32];
    const float g1a = g1[lane], g1b = g1[lane + 32];
    const float e1a = be1[lane], e1b = be1[lane + 32];

    // ---- one-time smem: layer2 params + LN coeffs + B operand (k-permuted) ----
    for (int i = tid; i < 128; i += TB) { B2s[i] = b2[i]; G2s[i] = g2[i]; BE2s[i] = be2[i]; }
    if (tid < 44) LNC[tid] = g_ln1[tid];
    for (int i = tid; i < 8192; i += TB) {
        int n = i & 127, k = i >> 7;
        int sk = ((k >> 3) << 3) + ((k & 3) << 1) + ((k >> 2) & 1);
        Bu[n * B_PITCH + sk] = f2tf32(w2[k * 128 + n]);
    }

    // ---- prologue: synchronous stage-0 for first tile into buffer 0 ----
    {
        int rbase = blockIdx.x * ROWS;
        if (tid < 128) {
            int r = rbase + tid;
            int bi = (r < N) ? bidx[r] : -1;
            SBIb[tid] = bi;
            float4 c4 = (bi >= 0) ? *(const float4*)(cond + 4 * bi)
                                  : make_float4(0.f, 0.f, 0.f, 0.f);
            *(float4*)(Csb + tid * 4) = c4;
        }
        for (int i = tid; i < 384; i += TB) {
            int gi = rbase * 3 + i;
            Xsb[i] = (gi < 3 * N) ? muons[gi] : 0.f;
        }
    }
    __syncthreads();

    const uint32_t xs_base  = smem_u32(Xsb);
    const uint32_t sbi_base = smem_u32(SBIb);

    int it = 0;
    for (int tile = blockIdx.x; tile < nTiles; tile += gridDim.x, it ^= 1) {
        const int   bufc = it, bufn = it ^ 1;
        const float* Xc  = Xsb + bufc * 384;
        const float* Cc  = Csb + bufc * 512;
        const int*   SBc = SBIb + bufc * 128;
        const int*   SBn = SBIb + bufn * 128;
        float*       Cn  = Csb + bufn * 512;

        const int  tnxt   = tile + gridDim.x;
        const bool vn     = tnxt < nTiles;
        const int  rbase2 = tnxt * ROWS;

        // ---- prefetch next tile's muons + batch_index ----
        if (vn) {
            if (tid < 96) {
                int gi = rbase2 * 3 + tid * 4;
                cp_async16(xs_base + (bufn * 384 + tid * 4) * 4, muons + gi, gi + 4 <= 3 * N);
            } else if (tid < 128) {
                int t2 = tid - 96;
                int gi = rbase2 + t2 * 4;
                cp_async16(sbi_base + (bufn * 128 + t2 * 4) * 4, bidx + gi, gi + 4 <= N);
            }
        }
        CP_COMMIT();

        // ---- event fast-path test (shared by stage 1 and stage 3) ----
        const int lr0   = wrp * 16;
        const int ebi0  = SBc[lr0];
        const int ebi15 = SBc[lr0 + 15];
        const bool sfast = (ebi0 == ebi15) && (ebi0 >= 0);

        // ---- stage 1: layer1 (7->64) + LN(64) + lrelu -> A (tf32, k-permuted) ----
        if (sfast) {
            // conditions constant across this warp's 16 rows: hoist everything
            const float4 cc = *(const float4*)(Cc + lr0 * 4);
            float base_a = b1a, base_b = b1b;
            base_a = fmaf(cc.x, w1a[3], base_a); base_b = fmaf(cc.x, w1b[3], base_b);
            base_a = fmaf(cc.y, w1a[4], base_a); base_b = fmaf(cc.y, w1b[4], base_b);
            base_a = fmaf(cc.z, w1a[5], base_a); base_b = fmaf(cc.z, w1b[5], base_b);
            base_a = fmaf(cc.w, w1a[6], base_a); base_b = fmaf(cc.w, w1b[6], base_b);
            float m_ev = LNC[42];
            m_ev = fmaf(cc.x, LNC[38], m_ev); m_ev = fmaf(cc.y, LNC[39], m_ev);
            m_ev = fmaf(cc.z, LNC[40], m_ev); m_ev = fmaf(cc.w, LNC[41], m_ev);
            const float mw0 = LNC[35], mw1 = LNC[36], mw2 = LNC[37];
            float l0 = LNC[28];
            l0 = fmaf(cc.x, LNC[3],  l0); l0 = fmaf(cc.y, LNC[4],  l0);
            l0 = fmaf(cc.z, LNC[5],  l0); l0 = fmaf(cc.w, LNC[6],  l0);
            float l1 = LNC[29];
            l1 = fmaf(cc.x, LNC[9],  l1); l1 = fmaf(cc.y, LNC[10], l1);
            l1 = fmaf(cc.z, LNC[11], l1); l1 = fmaf(cc.w, LNC[12], l1);
            float l2 = LNC[30];
            l2 = fmaf(cc.x, LNC[14], l2); l2 = fmaf(cc.y, LNC[15], l2);
            l2 = fmaf(cc.z, LNC[16], l2); l2 = fmaf(cc.w, LNC[17], l2);
            const float q00 = LNC[0], q01 = LNC[1], q02 = LNC[2];
            const float q11 = LNC[7], q12 = LNC[8], q22 = LNC[13];
            float q_ev = LNC[43];
            {
                float t3 = LNC[31];
                t3 = fmaf(cc.x, LNC[18], t3); t3 = fmaf(cc.y, LNC[19], t3);
                t3 = fmaf(cc.z, LNC[20], t3); t3 = fmaf(cc.w, LNC[21], t3);
                q_ev = fmaf(cc.x, t3, q_ev);
                float t4 = LNC[32];
                t4 = fmaf(cc.y, LNC[22], t4); t4 = fmaf(cc.z, LNC[23], t4);
                t4 = fmaf(cc.w, LNC[24], t4);
                q_ev = fmaf(cc.y, t4, q_ev);
                float t5 = LNC[33];
                t5 = fmaf(cc.z, LNC[25], t5); t5 = fmaf(cc.w, LNC[26], t5);
                q_ev = fmaf(cc.z, t5, q_ev);
                float t6 = fmaf(cc.w, LNC[27], LNC[34]);
                q_ev = fmaf(cc.w, t6, q_ev);
            }
            #pragma unroll 4
            for (int i = 0; i < 16; i++) {
                int lr = lr0 + i;
                float x0 = Xc[lr*3], x1 = Xc[lr*3+1], x2 = Xc[lr*3+2];
                float oa = fmaf(x2, w1a[2], fmaf(x1, w1a[1], fmaf(x0, w1a[0], base_a)));
                float ob = fmaf(x2, w1b[2], fmaf(x1, w1b[1], fmaf(x0, w1b[0], base_b)));
                float m  = fmaf(x2, mw2, fmaf(x1, mw1, fmaf(x0, mw0, m_ev)));
                float q  = q_ev;
                q = fmaf(x0, fmaf(x0, q00, l0), q);
                q = fmaf(x1, fmaf(x1, q11, fmaf(x0, q01, l1)), q);
                q = fmaf(x2, fmaf(x2, q22, fmaf(x1, q12, fmaf(x0, q02, l2))), q);
                float var  = fmaf(-m, m, q * (1.0f/64.0f));
                float rstd = rsqrtf(var + LN_EPS);
                float ha = lrelu(fmaf((oa - m) * rstd, g1a, e1a));
                float hb = lrelu(fmaf((ob - m) * rstd, g1b, e1b));
                Au[lr * A_PITCH + sidx]      = f2tf32(ha);
                Au[lr * A_PITCH + sidx + 32] = f2tf32(hb);
            }
        } else {
            // boundary / tail warp: original shuffle-reduction path
            #pragma unroll 4
            for (int i = 0; i < 16; i++) {
                int lr = lr0 + i;
                float x0 = Xc[lr*3], x1 = Xc[lr*3+1], x2 = Xc[lr*3+2];
                float4 cc = *(const float4*)(Cc + lr * 4);
                float oa = b1a, ob = b1b;
                oa = fmaf(x0,   w1a[0], oa);  ob = fmaf(x0,   w1b[0], ob);
                oa = fmaf(x1,   w1a[1], oa);  ob = fmaf(x1,   w1b[1], ob);
                oa = fmaf(x2,   w1a[2], oa);  ob = fmaf(x2,   w1b[2], ob);
                oa = fmaf(cc.x, w1a[3], oa);  ob = fmaf(cc.x, w1b[3], ob);
                oa = fmaf(cc.y, w1a[4], oa);  ob = fmaf(cc.y, w1b[4], ob);
                oa = fmaf(cc.z, w1a[5], oa);  ob = fmaf(cc.z, w1b[5], ob);
                oa = fmaf(cc.w, w1a[6], oa);  ob = fmaf(cc.w, w1b[6], ob);
                float s = oa + ob, q = oa*oa + ob*ob;
                #pragma unroll
                for (int d = 16; d; d >>= 1) {
                    s += __shfl_xor_sync(0xFFFFFFFFu, s, d);
                    q += __shfl_xor_sync(0xFFFFFFFFu, q, d);
                }
                float m    = s * (1.0f/64.0f);
                float var  = fmaf(-m, m, q * (1.0f/64.0f));
                float rstd = rsqrtf(var + LN_EPS);
                float ha = lrelu(fmaf((oa - m) * rstd, g1a, e1a));
                float hb = lrelu(fmaf((ob - m) * rstd, g1b, e1b));
                Au[lr * A_PITCH + sidx]      = f2tf32(ha);
                Au[lr * A_PITCH + sidx + 32] = f2tf32(hb);
            }
        }
        __syncwarp();   // stage-2 A reads are warp-local

        // ---- stage 2: GEMM 16x128x64 per warp, LDS.64 operands ----
        float acc[16][4];
        #pragma unroll
        for (int nt = 0; nt < 16; nt++)
            #pragma unroll
            for (int c = 0; c < 4; c++) acc[nt][c] = 0.f;

        const uint32_t* ap0 = Au + (wrp * 16 + quad) * A_PITCH + tig * 2;
        const uint32_t* ap1 = ap0 + 8 * A_PITCH;
        const uint32_t* bp  = Bu + quad * B_PITCH + tig * 2;
        #pragma unroll
        for (int ks = 0; ks < 8; ks++) {
            uint2 A0 = *(const uint2*)(ap0 + ks * 8);
            uint2 A1 = *(const uint2*)(ap1 + ks * 8);
            #pragma unroll
            for (int nt = 0; nt < 16; nt++) {
                uint2 Bv = *(const uint2*)(bp + nt * 8 * B_PITCH + ks * 8);
                mma_tf32(acc[nt][0], acc[nt][1], acc[nt][2], acc[nt][3],
                         A0.x, A1.x, A0.y, A1.y, Bv.x, Bv.y);
            }
        }

        // ---- stage 3a: bias + LN(128) stats (quad-local, registers) ----
        float sA = 0.f, qA = 0.f, sB = 0.f, qB = 0.f;
        #pragma unroll
        for (int nt = 0; nt < 16; nt++) {
            int col = nt * 8 + tig * 2;
            float2 bb = *(const float2*)(B2s + col);
            acc[nt][0] += bb.x; acc[nt][1] += bb.y;
            acc[nt][2] += bb.x; acc[nt][3] += bb.y;
            sA += acc[nt][0] + acc[nt][1];
            qA = fmaf(acc[nt][0], acc[nt][0], fmaf(acc[nt][1], acc[nt][1], qA));
            sB += acc[nt][2] + acc[nt][3];
            qB = fmaf(acc[nt][2], acc[nt][2], fmaf(acc[nt][3], acc[nt][3], qB));
        }
        #pragma unroll
        for (int d = 1; d <= 2; d <<= 1) {
            sA += __shfl_xor_sync(0xFFFFFFFFu, sA, d);
            qA += __shfl_xor_sync(0xFFFFFFFFu, qA, d);
            sB += __shfl_xor_sync(0xFFFFFFFFu, sB, d);
            qB += __shfl_xor_sync(0xFFFFFFFFu, qB, d);
        }
        float mA  = sA * (1.0f/128.0f);
        float rsA = rsqrtf(fmaf(-mA, mA, qA * (1.0f/128.0f)) + LN_EPS);
        float mB  = sB * (1.0f/128.0f);
        float rsB = rsqrtf(fmaf(-mB, mB, qB * (1.0f/128.0f)) + LN_EPS);

        // ---- stage 3b+3c: normalize + lrelu + nan guard, pool from registers ----
        const int ra = lr0 + quad;
        const int rb = ra + 8;
        const int bi_ra = SBc[ra];
        const int bi_rb = SBc[rb];
        float* const Wme = Wst + wrp * (16 * A_PITCH);   // warp-private staging (own A rows)

        #pragma unroll
        for (int nt = 0; nt < 16; nt++) {
            int col = nt * 8 + tig * 2;
            float2 gg = *(const float2*)(G2s + col);
            float2 ee = *(const float2*)(BE2s + col);
            float v0 = lrelu(fmaf((acc[nt][0] - mA) * rsA, gg.x, ee.x));
            float v1 = lrelu(fmaf((acc[nt][1] - mA) * rsA, gg.y, ee.y));
            float v2 = lrelu(fmaf((acc[nt][2] - mB) * rsB, gg.x, ee.x));
            float v3 = lrelu(fmaf((acc[nt][3] - mB) * rsB, gg.y, ee.y));
            if (!isfinite(v0)) v0 = 0.f;
            if (!isfinite(v1)) v1 = 0.f;
            if (!isfinite(v2)) v2 = 0.f;
            if (!isfinite(v3)) v3 = 0.f;
            if (sfast) {
                float m0 = fmaxf(v0, v2), m1 = fmaxf(v1, v3);
                #pragma unroll
                for (int d = 4; d <= 16; d <<= 1) {
                    m0 = fmaxf(m0, __shfl_xor_sync(0xFFFFFFFFu, m0, d));
                    m1 = fmaxf(m1, __shfl_xor_sync(0xFFFFFFFFu, m1, d));
                }
                if (quad == 0) *(float2*)(Wme + col) = make_float2(m0, m1);
            } else {
                if (bi_ra >= 0) {
                    atomicMax(&g_gf_enc[bi_ra * 128 + col],     enc_f(v0));
                    atomicMax(&g_gf_enc[bi_ra * 128 + col + 1], enc_f(v1));
                }
                if (bi_rb >= 0) {
                    atomicMax(&g_gf_enc[bi_rb * 128 + col],     enc_f(v2));
                    atomicMax(&g_gf_enc[bi_rb * 128 + col + 1], enc_f(v3));
                }
            }
        }
        if (lane == 0) Ewp[wrp] = sfast ? ebi0 : -1;

        CP_WAIT0();
        __syncthreads();   // Wst/Ewp visible; prefetched buffers visible

        // ---- gather next tile's conditions (loads overlap combine below) ----
        float4 c4n = make_float4(0.f, 0.f, 0.f, 0.f);
        int bin = -1;
        if (vn && tid < 128) {
            if (rbase2 + ROWS > N) bin = (rbase2 + tid < N) ? bidx[rbase2 + tid] : -1;
            else bin = SBn[tid];
            if (bin >= 0) c4n = *(const float4*)(cond + 4 * bin);
        }

        // ---- combine per-warp partials (run-length over 8 warps) ----
        if (tid < 128) {
            int   cure = -1;
            float cur  = -3.0e38f;
            #pragma unroll
            for (int w = 0; w < 8; w++) {
                int e = Ewp[w];
                if (e >= 0) {
                    float v = Wst[w * (16 * A_PITCH) + tid];
                    if (e != cure) {
                        if (cure >= 0) atomicMax(&g_gf_enc[cure * 128 + tid], enc_f(cur));
                        cure = e; cur = v;
                    } else {
                        cur = fmaxf(cur, v);
                    }
                }
            }
            if (cure >= 0) atomicMax(&g_gf_enc[cure * 128 + tid], enc_f(cur));
        }
        if (vn && tid < 128) {
            *(float4*)(Cn + tid * 4) = c4n;
            if (rbase2 + ROWS > N) ((int*)SBn)[tid] = bin;   // tail fixup
        }
        if (vn && rbase2 + ROWS > N) {
            for (int i = tid; i < 384; i += TB) {
                int gi = rbase2 * 3 + i;
                Xsb[bufn * 384 + i] = (gi < 3 * N) ? muons[gi] : 0.f;
            }
        }
        __syncthreads();   // A/Wst + Cn/SBn reuse barrier
    }
}

// ---------------- kernel C: decision net ----------------
__global__ __launch_bounds__(256) void k_dec(
    const float* __restrict__ cond,
    const float* __restrict__ w3, const float* __restrict__ b3,
    const float* __restrict__ g3, const float* __restrict__ be3,
    const float* __restrict__ w4, const float* __restrict__ b4,
    const float* __restrict__ g4, const float* __restrict__ be4,
    const float* __restrict__ w5, const float* __restrict__ b5,
    int B)
{
    extern __shared__ float sm[];
    float* W3 = sm;
    float* W4 = W3 + 16896;
    float* W5 = W4 + 8192;
    float* B3 = W5 + 64;
    float* G3 = B3 + 128;
    float* BE3= G3 + 128;
    float* B4 = BE3 + 128;
    float* G4 = B4 + 64;
    float* BE4= G4 + 64;
    float* XB = BE4 + 64;

    const int tid = threadIdx.x, lane = tid & 31, wrp = tid >> 5;
    for (int i = tid; i < 16896; i += 256) W3[i] = w3[i];
    for (int i = tid; i < 8192;  i += 256) W4[i] = w4[i];
    for (int i = tid; i < 64;    i += 256) { W5[i] = w5[i]; B4[i] = b4[i]; G4[i] = g4[i]; BE4[i] = be4[i]; }
    for (int i = tid; i < 128;   i += 256) { B3[i] = b3[i]; G3[i] = g3[i]; BE3[i] = be3[i]; }
    __syncthreads();

    float* xb = XB + wrp * 136;
    const float b5v = b5[0];

    #pragma unroll 1
    for (int i = 0; i < 4; i++) {
        int row = (blockIdx.x * 8 + wrp) * 4 + i;
        if (row >= B) break;
        __syncwarp();
        #pragma unroll
        for (int j = 0; j < 4; j++) {
            float v = dec_f(g_gf_enc[row*128 + lane + 32*j]);
            if (isnan(v)) v = NEG_FILL;
            else if (isinf(v)) v = (v > 0.f) ? 1.0e9f : NEG_FILL;
            xb[lane + 32*j] = v;
        }
        if (lane < 4) xb[128 + lane] = cond[row*4 + lane];
        __syncwarp();

        float a0 = B3[lane], a1 = B3[lane+32], a2 = B3[lane+64], a3 = B3[lane+96];
        #pragma unroll 4
        for (int k = 0; k < 132; k++) {
            float xk = xb[k];
            const float* wr = W3 + k*128;
            a0 = fmaf(xk, wr[lane],      a0);
            a1 = fmaf(xk, wr[lane+32],   a1);
            a2 = fmaf(xk, wr[lane+64],   a2);
            a3 = fmaf(xk, wr[lane+96],   a3);
        }
        float s = a0+a1+a2+a3;
        float q = a0*a0 + a1*a1 + a2*a2 + a3*a3;
        #pragma unroll
        for (int d = 16; d; d >>= 1) {
            s += __shfl_xor_sync(0xFFFFFFFFu, s, d);
            q += __shfl_xor_sync(0xFFFFFFFFu, q, d);
        }
        float m = s * (1.0f/128.0f);
        float var = fmaf(-m, m, q * (1.0f/128.0f));
        float rs = rsqrtf(var + LN_EPS);
        a0 = lrelu(fmaf((a0-m)*rs, G3[lane],    BE3[lane]));
        a1 = lrelu(fmaf((a1-m)*rs, G3[lane+32], BE3[lane+32]));
        a2 = lrelu(fmaf((a2-m)*rs, G3[lane+64], BE3[lane+64]));
        a3 = lrelu(fmaf((a3-m)*rs, G3[lane+96], BE3[lane+96]));
        __syncwarp();
        xb[lane] = a0; xb[lane+32] = a1; xb[lane+64] = a2; xb[lane+96] = a3;
        __syncwarp();

        float c0v = B4[lane], c1v = B4[lane+32];
        #pragma unroll 4
        for (int k = 0; k < 128; k++) {
            float xk = xb[k];
            c0v = fmaf(xk, W4[k*64 + lane],      c0v);
            c1v = fmaf(xk, W4[k*64 + lane + 32], c1v);
        }
        s = c0v + c1v;
        q = c0v*c0v + c1v*c1v;
        #pragma unroll
        for (int d = 16; d; d >>= 1) {
            s += __shfl_xor_sync(0xFFFFFFFFu, s, d);
            q += __shfl_xor_sync(0xFFFFFFFFu, q, d);
        }
        m = s * (1.0f/64.0f);
        var = fmaf(-m, m, q * (1.0f/64.0f));
        rs = rsqrtf(var + LN_EPS);
        c0v = lrelu(fmaf((c0v-m)*rs, G4[lane],    BE4[lane]));
        c1v = lrelu(fmaf((c1v-m)*rs, G4[lane+32], BE4[lane+32]));

        float p = c0v * W5[lane] + c1v * W5[lane+32];
        #pragma unroll
        for (int d = 16; d; d >>= 1) p += __shfl_xor_sync(0xFFFFFFFFu, p, d);
        if (lane == 0) g_score[row] = p + b5v;
    }
}

// ---------------- kernel D: EMA normalize + tanh ----------------
__global__ void k_final(float* __restrict__ out, int B) {
    __shared__ float red[1024];
    int tid = threadIdx.x;
    float s = 0.f;
    for (int i = tid; i < B; i += 1024) s += fabsf(g_score[i]);
    red[tid] = s;
    __syncthreads();
    #pragma unroll
    for (int d = 512; d; d >>= 1) {
        if (tid < d) red[tid] += red[tid + d];
        __syncthreads();
    }
    float mean  = red[0] / (float)B;
    float ema   = 0.99f + 0.01f * mean;
    float denom = fmaxf(ema, 0.1f);
    for (int i = tid; i < B; i += 1024) {
        float sc = g_score[i] / denom;
        sc = fminf(fmaxf(sc, -5.0f), 5.0f);
        out[i] = 10.0f * tanhf(sc * 0.2f);
    }
}

// ---------------- launch ----------------
extern "C" void kernel_launch(void* const* d_in, const int* in_sizes, int n_in,
                              void* d_out, int out_size) {
    const float* muons = (const float*)d_in[0];
    const int*   bidx  = (const int*)  d_in[1];
    const float* cond  = (const float*)d_in[2];
    const float* w1  = (const float*)d_in[4];
    const float* b1  = (const float*)d_in[5];
    const float* g1  = (const float*)d_in[6];
    const float* be1 = (const float*)d_in[7];
    const float* w2  = (const float*)d_in[8];
    const float* b2  = (const float*)d_in[9];
    const float* g2  = (const float*)d_in[10];
    const float* be2 = (const float*)d_in[11];
    const float* w3  = (const float*)d_in[12];
    const float* b3  = (const float*)d_in[13];
    const float* g3  = (const float*)d_in[14];
    const float* be3 = (const float*)d_in[15];
    const float* w4  = (const float*)d_in[16];
    const float* b4  = (const float*)d_in[17];
    const float* g4  = (const float*)d_in[18];
    const float* be4 = (const float*)d_in[19];
    const float* w5  = (const float*)d_in[20];
    const float* b5  = (const float*)d_in[21];

    int N = in_sizes[0] / 3;
    int B = in_sizes[2] / 4;
    if (B > MAXB) B = MAXB;

    static const size_t SMEM_DEC = (size_t)(16896 + 8192 + 64 + 128*3 + 64*3 + 8*136) * 4;
    cudaFuncSetAttribute(k_main, cudaFuncAttributeMaxDynamicSharedMemorySize, (int)SMEM_NEED);
    cudaFuncSetAttribute(k_dec,  cudaFuncAttributeMaxDynamicSharedMemorySize, (int)SMEM_DEC);

    int initN = B * 128;
    k_init<<<(initN + 255) / 256, 256>>>(initN, w1, b1);

    int nTiles = (N + ROWS - 1) / ROWS;
    int nBlocks = 2 * 148;
    if (nBlocks > nTiles) nBlocks = nTiles;
    k_main<<<nBlocks, TB, SMEM_NEED>>>(muons, bidx, cond,
                                       w1, b1, g1, be1, w2, b2, g2, be2, N, nTiles);

    int decBlocks = (B + 31) / 32;
    k_dec<<<decBlocks, 256, SMEM_DEC>>>(cond, w3, b3, g3, be3,
                                        w4, b4, g4, be4, w5, b5, B);

    k_final<<<1, 1024>>>((float*)d_out, B);
}

// round 8
// speedup vs baseline: 2.6506x; 1.2836x over previous
#include <cuda_runtime.h>
#include <cuda_fp16.h>
#include <math.h>
#include <cstdint>

#define LN_EPS 1e-5f
#define NEG_FILL -1.0e9f
#define MAXB 8192

// ---------------- device scratch ----------------
__device__ unsigned g_gf_enc[MAXB * 128];
__device__ float    g_score[MAXB];
__device__ float    g_ln1[44];   // closed-form LN(64) coefficients

// ---------------- helpers ----------------
__device__ __forceinline__ unsigned enc_f(float f) {
    int i = __float_as_int(f);
    unsigned u = (unsigned)i;
    return (i < 0) ? ~u : (u | 0x80000000u);
}
__device__ __forceinline__ float dec_f(unsigned u) {
    return (u & 0x80000000u) ? __int_as_float((int)(u & 0x7FFFFFFFu))
                             : __int_as_float((int)(~u));
}
__device__ __forceinline__ float lrelu(float v) { return v >= 0.0f ? v : 0.2f * v; }
__device__ __forceinline__ uint32_t smem_u32(const void* p) {
    return (uint32_t)__cvta_generic_to_shared(p);
}
__device__ __forceinline__ void cp_async16(uint32_t dst, const void* src, bool full) {
    int sz = full ? 16 : 0;
    asm volatile("cp.async.cg.shared.global [%0], [%1], 16, %2;"
                 :: "r"(dst), "l"(src), "r"(sz));
}
#define CP_COMMIT() asm volatile("cp.async.commit_group;" ::: "memory")
#define CP_WAIT0()  asm volatile("cp.async.wait_group 0;" ::: "memory")

// fp16 warp MMA: D(16x8,f32) += A(16x16,f16) * B(16x8,f16)
__device__ __forceinline__ void mma_f16(float& c0, float& c1, float& c2, float& c3,
                                        uint32_t a0, uint32_t a1, uint32_t a2, uint32_t a3,
                                        uint32_t b0, uint32_t b1) {
    asm volatile(
        "mma.sync.aligned.m16n8k16.row.col.f32.f16.f16.f32 "
        "{%0,%1,%2,%3}, {%4,%5,%6,%7}, {%8,%9}, {%0,%1,%2,%3};"
        : "+f"(c0), "+f"(c1), "+f"(c2), "+f"(c3)
        : "r"(a0), "r"(a1), "r"(a2), "r"(a3), "r"(b0), "r"(b1));
}

// k-pair permuted half index within a row of 64 halves:
// chunk(k>>4)*16 + pair-interleave so lane t LDS.64 -> pairs (t, t+4) = {a0,a2}/{b0,b1}
__device__ __host__ __forceinline__ int sidx16(int k) {
    return ((k >> 4) << 4) | ((((k >> 1) & 3) << 2) | (((k >> 3) & 1) << 1) | (k & 1));
}

// ---------------- kernel A: init pooled buffer + LN coefficients ----------------
// LN coeff layout (idx(j,k)=off(j)+(k-j), off={0,7,13,18,22,25,27}):
//  [0..27] qc | [28..34] twod | [35..41] mw | [42] mb | [43] S0
__global__ void k_init(int n, const float* __restrict__ w1, const float* __restrict__ b1) {
    int i = blockIdx.x * blockDim.x + threadIdx.x;
    if (i < n) g_gf_enc[i] = enc_f(NEG_FILL);
    if (blockIdx.x == 0 && threadIdx.x < 44) {
        int t = threadIdx.x;
        float v = 0.f;
        if (t < 28) {
            int j = 0, k = 0, idx = t;
            #pragma unroll 1
            for (j = 0; j < 7; j++) { int len = 7 - j; if (idx < len) { k = j + idx; break; } idx -= len; }
            float s = 0.f;
            for (int e = 0; e < 64; e++) s = fmaf(w1[j*64+e], w1[k*64+e], s);
            v = (j == k) ? s : 2.0f * s;
        } else if (t < 35) {
            int j = t - 28;
            float s = 0.f;
            for (int e = 0; e < 64; e++) s = fmaf(b1[e], w1[j*64+e], s);
            v = 2.0f * s;
        } else if (t < 42) {
            int j = t - 35;
            float s = 0.f;
            for (int e = 0; e < 64; e++) s += w1[j*64+e];
            v = s * (1.0f/64.0f);
        } else if (t == 42) {
            float s = 0.f;
            for (int e = 0; e < 64; e++) s += b1[e];
            v = s * (1.0f/64.0f);
        } else {
            float s = 0.f;
            for (int e = 0; e < 64; e++) s = fmaf(b1[e], b1[e], s);
            v = s;
        }
        g_ln1[t] = v;
    }
}

// ---------------- k_main layout ----------------
#define TB 256
#define ROWS 128
#define AP_H 80              // halves per row (160B = 40 words; conflict-free frags)
#define WST_STRIDE 640       // floats per warp staging region (16*80 halves)
#define OFF_B    20480                 // A: 128*80*2
#define OFF_PARM (20480 + 20480)       // B: 128*80*2
// params (floats): B2s 128 | G2s 128 | BE2s 128 | SBI 2*128(int) | Xs 2*384 | Cs 2*512 | Ewp 8(int) | LNC 44
#define SMEM_NEED (OFF_PARM + 2484 * 4)

__global__ __launch_bounds__(256, 2) void k_main(
    const float* __restrict__ muons, const int* __restrict__ bidx,
    const float* __restrict__ cond,
    const float* __restrict__ w1, const float* __restrict__ b1,
    const float* __restrict__ g1, const float* __restrict__ be1,
    const float* __restrict__ w2, const float* __restrict__ b2,
    const float* __restrict__ g2, const float* __restrict__ be2,
    int N, int nTiles)
{
    extern __shared__ char base[];
    __half* const Ah   = (__half*)(base);            // A operand (f16, k-permuted)
    float*  const Wst  = (float*)(base);             // per-warp col-max staging (aliases A)
    __half* const Bh   = (__half*)(base + OFF_B);    // B operand (f16, k-permuted)
    float*  const PR   = (float*)(base + OFF_PARM);
    float* const B2s  = PR;            // 128
    float* const G2s  = B2s + 128;     // 128
    float* const BE2s = G2s + 128;     // 128
    int*   const SBIb = (int*)(BE2s + 128);   // 2*128
    float* const Xsb  = (float*)(SBIb + 256); // 2*384
    float* const Csb  = Xsb + 768;            // 2*512
    int*   const Ewp  = (int*)(Csb + 1024);   // 8
    float* const LNC  = (float*)(Ewp + 8);    // 44

    const int tid  = threadIdx.x;
    const int lane = tid & 31;
    const int wrp  = tid >> 5;
    const int quad = lane >> 2;
    const int tig  = lane & 3;
    const int s16  = sidx16(lane);   // store index for k=lane (k=lane+32 -> +32)

    // ---- per-lane constant layer1 params in registers ----
    float w1a[7], w1b[7];
    #pragma unroll
    for (int j = 0; j < 7; j++) { w1a[j] = w1[j*64 + lane]; w1b[j] = w1[j*64 + lane + 32]; }
    const float b1a = b1[lane], b1b = b1[lane + 32];
    const float g1a = g1[lane], g1b = g1[lane + 32];
    const float e1a = be1[lane], e1b = be1[lane + 32];

    // ---- one-time smem: layer2 params + LN coeffs + B operand (f16, k-permuted) ----
    for (int i = tid; i < 128; i += TB) { B2s[i] = b2[i]; G2s[i] = g2[i]; BE2s[i] = be2[i]; }
    if (tid < 44) LNC[tid] = g_ln1[tid];
    for (int i = tid; i < 8192; i += TB) {
        int n = i & 127, k = i >> 7;
        Bh[n * AP_H + sidx16(k)] = __float2half_rn(w2[k * 128 + n]);
    }

    // ---- prologue: synchronous stage-0 for first tile into buffer 0 ----
    {
        int rbase = blockIdx.x * ROWS;
        if (tid < 128) {
            int r = rbase + tid;
            int bi = (r < N) ? bidx[r] : -1;
            SBIb[tid] = bi;
            float4 c4 = (bi >= 0) ? *(const float4*)(cond + 4 * bi)
                                  : make_float4(0.f, 0.f, 0.f, 0.f);
            *(float4*)(Csb + tid * 4) = c4;
        }
        for (int i = tid; i < 384; i += TB) {
            int gi = rbase * 3 + i;
            Xsb[i] = (gi < 3 * N) ? muons[gi] : 0.f;
        }
    }
    __syncthreads();

    const uint32_t xs_base  = smem_u32(Xsb);
    const uint32_t sbi_base = smem_u32(SBIb);

    int it = 0;
    for (int tile = blockIdx.x; tile < nTiles; tile += gridDim.x, it ^= 1) {
        const int   bufc = it, bufn = it ^ 1;
        const float* Xc  = Xsb + bufc * 384;
        const float* Cc  = Csb + bufc * 512;
        const int*   SBc = SBIb + bufc * 128;
        const int*   SBn = SBIb + bufn * 128;
        float*       Cn  = Csb + bufn * 512;

        const int  tnxt   = tile + gridDim.x;
        const bool vn     = tnxt < nTiles;
        const int  rbase2 = tnxt * ROWS;

        // ---- prefetch next tile's muons + batch_index ----
        if (vn) {
            if (tid < 96) {
                int gi = rbase2 * 3 + tid * 4;
                cp_async16(xs_base + (bufn * 384 + tid * 4) * 4, muons + gi, gi + 4 <= 3 * N);
            } else if (tid < 128) {
                int t2 = tid - 96;
                int gi = rbase2 + t2 * 4;
                cp_async16(sbi_base + (bufn * 128 + t2 * 4) * 4, bidx + gi, gi + 4 <= N);
            }
        }
        CP_COMMIT();

        // ---- event fast-path test ----
        const int lr0   = wrp * 16;
        const int ebi0  = SBc[lr0];
        const int ebi15 = SBc[lr0 + 15];
        const bool sfast = (ebi0 == ebi15) && (ebi0 >= 0);

        // ---- stage 1: layer1 (7->64) + closed-form LN(64) + lrelu -> A (f16) ----
        if (sfast) {
            // conditions constant across this warp's 16 rows: hoist c-dependent parts
            const float4 cc = *(const float4*)(Cc + lr0 * 4);
            float base_a = b1a, base_b = b1b;
            base_a = fmaf(cc.x, w1a[3], base_a); base_b = fmaf(cc.x, w1b[3], base_b);
            base_a = fmaf(cc.y, w1a[4], base_a); base_b = fmaf(cc.y, w1b[4], base_b);
            base_a = fmaf(cc.z, w1a[5], base_a); base_b = fmaf(cc.z, w1b[5], base_b);
            base_a = fmaf(cc.w, w1a[6], base_a); base_b = fmaf(cc.w, w1b[6], base_b);
            float m_ev = LNC[42];
            m_ev = fmaf(cc.x, LNC[38], m_ev); m_ev = fmaf(cc.y, LNC[39], m_ev);
            m_ev = fmaf(cc.z, LNC[40], m_ev); m_ev = fmaf(cc.w, LNC[41], m_ev);
            const float mw0 = LNC[35], mw1 = LNC[36], mw2 = LNC[37];
            float l0 = LNC[28];
            l0 = fmaf(cc.x, LNC[3],  l0); l0 = fmaf(cc.y, LNC[4],  l0);
            l0 = fmaf(cc.z, LNC[5],  l0); l0 = fmaf(cc.w, LNC[6],  l0);
            float l1 = LNC[29];
            l1 = fmaf(cc.x, LNC[9],  l1); l1 = fmaf(cc.y, LNC[10], l1);
            l1 = fmaf(cc.z, LNC[11], l1); l1 = fmaf(cc.w, LNC[12], l1);
            float l2 = LNC[30];
            l2 = fmaf(cc.x, LNC[14], l2); l2 = fmaf(cc.y, LNC[15], l2);
            l2 = fmaf(cc.z, LNC[16], l2); l2 = fmaf(cc.w, LNC[17], l2);
            const float q00 = LNC[0], q01 = LNC[1], q02 = LNC[2];
            const float q11 = LNC[7], q12 = LNC[8], q22 = LNC[13];
            float q_ev = LNC[43];
            {
                float t3 = LNC[31];
                t3 = fmaf(cc.x, LNC[18], t3); t3 = fmaf(cc.y, LNC[19], t3);
                t3 = fmaf(cc.z, LNC[20], t3); t3 = fmaf(cc.w, LNC[21], t3);
                q_ev = fmaf(cc.x, t3, q_ev);
                float t4 = LNC[32];
                t4 = fmaf(cc.y, LNC[22], t4); t4 = fmaf(cc.z, LNC[23], t4);
                t4 = fmaf(cc.w, LNC[24], t4);
                q_ev = fmaf(cc.y, t4, q_ev);
                float t5 = LNC[33];
                t5 = fmaf(cc.z, LNC[25], t5); t5 = fmaf(cc.w, LNC[26], t5);
                q_ev = fmaf(cc.z, t5, q_ev);
                float t6 = fmaf(cc.w, LNC[27], LNC[34]);
                q_ev = fmaf(cc.w, t6, q_ev);
            }
            #pragma unroll 4
            for (int i = 0; i < 16; i++) {
                int lr = lr0 + i;
                float x0 = Xc[lr*3], x1 = Xc[lr*3+1], x2 = Xc[lr*3+2];
                float oa = fmaf(x2, w1a[2], fmaf(x1, w1a[1], fmaf(x0, w1a[0], base_a)));
                float ob = fmaf(x2, w1b[2], fmaf(x1, w1b[1], fmaf(x0, w1b[0], base_b)));
                float m  = fmaf(x2, mw2, fmaf(x1, mw1, fmaf(x0, mw0, m_ev)));
                float q  = q_ev;
                q = fmaf(x0, fmaf(x0, q00, l0), q);
                q = fmaf(x1, fmaf(x1, q11, fmaf(x0, q01, l1)), q);
                q = fmaf(x2, fmaf(x2, q22, fmaf(x1, q12, fmaf(x0, q02, l2))), q);
                float var  = fmaf(-m, m, q * (1.0f/64.0f));
                float rstd = rsqrtf(var + LN_EPS);
                float ha = lrelu(fmaf((oa - m) * rstd, g1a, e1a));
                float hb = lrelu(fmaf((ob - m) * rstd, g1b, e1b));
                Ah[lr * AP_H + s16]      = __float2half_rn(ha);
                Ah[lr * AP_H + s16 + 32] = __float2half_rn(hb);
            }
        } else {
            // boundary / tail warp: per-row closed-form LN (no shuffles)
            const int off7[7] = {0, 7, 13, 18, 22, 25, 27};
            #pragma unroll 2
            for (int i = 0; i < 16; i++) {
                int lr = lr0 + i;
                float4 cc = *(const float4*)(Cc + lr * 4);
                float z[7];
                z[0] = Xc[lr*3]; z[1] = Xc[lr*3+1]; z[2] = Xc[lr*3+2];
                z[3] = cc.x; z[4] = cc.y; z[5] = cc.z; z[6] = cc.w;
                float oa = b1a, ob = b1b;
                #pragma unroll
                for (int j = 0; j < 7; j++) {
                    oa = fmaf(z[j], w1a[j], oa);
                    ob = fmaf(z[j], w1b[j], ob);
                }
                float m = LNC[42];
                #pragma unroll
                for (int j = 0; j < 7; j++) m = fmaf(z[j], LNC[35 + j], m);
                float q = LNC[43];
                #pragma unroll
                for (int j = 0; j < 7; j++) {
                    float t = LNC[28 + j];
                    #pragma unroll
                    for (int k = j; k < 7; k++) t = fmaf(z[k], LNC[off7[j] + k - j], t);
                    q = fmaf(z[j], t, q);
                }
                float var  = fmaf(-m, m, q * (1.0f/64.0f));
                float rstd = rsqrtf(var + LN_EPS);
                float ha = lrelu(fmaf((oa - m) * rstd, g1a, e1a));
                float hb = lrelu(fmaf((ob - m) * rstd, g1b, e1b));
                Ah[lr * AP_H + s16]      = __float2half_rn(ha);
                Ah[lr * AP_H + s16 + 32] = __float2half_rn(hb);
            }
        }
        __syncwarp();   // stage-2 A reads are warp-local

        // ---- stage 2: GEMM 16x128x64 per warp via m16n8k16.f16 ----
        float acc[16][4];
        #pragma unroll
        for (int nt = 0; nt < 16; nt++)
            #pragma unroll
            for (int c = 0; c < 4; c++) acc[nt][c] = 0.f;

        const __half* ap0 = Ah + (wrp * 16 + quad) * AP_H + tig * 4;
        const __half* ap1 = ap0 + 8 * AP_H;
        const __half* bp  = Bh + quad * AP_H + tig * 4;
        #pragma unroll
        for (int ks = 0; ks < 4; ks++) {
            uint2 A0 = *(const uint2*)(ap0 + ks * 16);   // {a0, a2} rows q
            uint2 A1 = *(const uint2*)(ap1 + ks * 16);   // {a1, a3} rows q+8
            #pragma unroll
            for (int nt = 0; nt < 16; nt++) {
                uint2 Bv = *(const uint2*)(bp + nt * 8 * AP_H + ks * 16);  // {b0, b1}
                mma_f16(acc[nt][0], acc[nt][1], acc[nt][2], acc[nt][3],
                        A0.x, A1.x, A0.y, A1.y, Bv.x, Bv.y);
            }
        }

        // ---- stage 3a: bias + LN(128) stats (quad-local, registers) ----
        float sA = 0.f, qA = 0.f, sB = 0.f, qB = 0.f;
        #pragma unroll
        for (int nt = 0; nt < 16; nt++) {
            int col = nt * 8 + tig * 2;
            float2 bb = *(const float2*)(B2s + col);
            acc[nt][0] += bb.x; acc[nt][1] += bb.y;
            acc[nt][2] += bb.x; acc[nt][3] += bb.y;
            sA += acc[nt][0] + acc[nt][1];
            qA = fmaf(acc[nt][0], acc[nt][0], fmaf(acc[nt][1], acc[nt][1], qA));
            sB += acc[nt][2] + acc[nt][3];
            qB = fmaf(acc[nt][2], acc[nt][2], fmaf(acc[nt][3], acc[nt][3], qB));
        }
        #pragma unroll
        for (int d = 1; d <= 2; d <<= 1) {
            sA += __shfl_xor_sync(0xFFFFFFFFu, sA, d);
            qA += __shfl_xor_sync(0xFFFFFFFFu, qA, d);
            sB += __shfl_xor_sync(0xFFFFFFFFu, sB, d);
            qB += __shfl_xor_sync(0xFFFFFFFFu, qB, d);
        }
        float mA  = sA * (1.0f/128.0f);
        float rsA = rsqrtf(fmaf(-mA, mA, qA * (1.0f/128.0f)) + LN_EPS);
        float mB  = sB * (1.0f/128.0f);
        float rsB = rsqrtf(fmaf(-mB, mB, qB * (1.0f/128.0f)) + LN_EPS);

        // ---- stage 3b+3c: normalize + lrelu + nan guard, pool from registers ----
        const int ra = lr0 + quad;
        const int rb = ra + 8;
        const int bi_ra = SBc[ra];
        const int bi_rb = SBc[rb];
        float* const Wme = Wst + wrp * WST_STRIDE;

        #pragma unroll
        for (int nt = 0; nt < 16; nt++) {
            int col = nt * 8 + tig * 2;
            float2 gg = *(const float2*)(G2s + col);
            float2 ee = *(const float2*)(BE2s + col);
            float v0 = lrelu(fmaf((acc[nt][0] - mA) * rsA, gg.x, ee.x));
            float v1 = lrelu(fmaf((acc[nt][1] - mA) * rsA, gg.y, ee.y));
            float v2 = lrelu(fmaf((acc[nt][2] - mB) * rsB, gg.x, ee.x));
            float v3 = lrelu(fmaf((acc[nt][3] - mB) * rsB, gg.y, ee.y));
            if (!isfinite(v0)) v0 = 0.f;
            if (!isfinite(v1)) v1 = 0.f;
            if (!isfinite(v2)) v2 = 0.f;
            if (!isfinite(v3)) v3 = 0.f;
            if (sfast) {
                float m0 = fmaxf(v0, v2), m1 = fmaxf(v1, v3);
                #pragma unroll
                for (int d = 4; d <= 16; d <<= 1) {
                    m0 = fmaxf(m0, __shfl_xor_sync(0xFFFFFFFFu, m0, d));
                    m1 = fmaxf(m1, __shfl_xor_sync(0xFFFFFFFFu, m1, d));
                }
                if (quad == 0) *(float2*)(Wme + col) = make_float2(m0, m1);
            } else {
                if (bi_ra >= 0) {
                    atomicMax(&g_gf_enc[bi_ra * 128 + col],     enc_f(v0));
                    atomicMax(&g_gf_enc[bi_ra * 128 + col + 1], enc_f(v1));
                }
                if (bi_rb >= 0) {
                    atomicMax(&g_gf_enc[bi_rb * 128 + col],     enc_f(v2));
                    atomicMax(&g_gf_enc[bi_rb * 128 + col + 1], enc_f(v3));
                }
            }
        }
        if (lane == 0) Ewp[wrp] = sfast ? ebi0 : -1;

        CP_WAIT0();
        __syncthreads();   // Wst/Ewp visible; prefetched buffers visible

        // ---- gather next tile's conditions (loads overlap combine below) ----
        float4 c4n = make_float4(0.f, 0.f, 0.f, 0.f);
        int bin = -1;
        if (vn && tid < 128) {
            if (rbase2 + ROWS > N) bin = (rbase2 + tid < N) ? bidx[rbase2 + tid] : -1;
            else bin = SBn[tid];
            if (bin >= 0) c4n = *(const float4*)(cond + 4 * bin);
        }

        // ---- combine per-warp partials (run-length over 8 warps) ----
        if (tid < 128) {
            int   cure = -1;
            float cur  = -3.0e38f;
            #pragma unroll
            for (int w = 0; w < 8; w++) {
                int e = Ewp[w];
                if (e >= 0) {
                    float v = Wst[w * WST_STRIDE + tid];
                    if (e != cure) {
                        if (cure >= 0) atomicMax(&g_gf_enc[cure * 128 + tid], enc_f(cur));
                        cure = e; cur = v;
                    } else {
                        cur = fmaxf(cur, v);
                    }
                }
            }
            if (cure >= 0) atomicMax(&g_gf_enc[cure * 128 + tid], enc_f(cur));
        }
        if (vn && tid < 128) {
            *(float4*)(Cn + tid * 4) = c4n;
            if (rbase2 + ROWS > N) ((int*)SBn)[tid] = bin;   // tail fixup
        }
        if (vn && rbase2 + ROWS > N) {
            for (int i = tid; i < 384; i += TB) {
                int gi = rbase2 * 3 + i;
                Xsb[bufn * 384 + i] = (gi < 3 * N) ? muons[gi] : 0.f;
            }
        }
        __syncthreads();   // A/Wst + Cn/SBn reuse barrier
    }
}

// ---------------- kernel C: decision net ----------------
__global__ __launch_bounds__(256) void k_dec(
    const float* __restrict__ cond,
    const float* __restrict__ w3, const float* __restrict__ b3,
    const float* __restrict__ g3, const float* __restrict__ be3,
    const float* __restrict__ w4, const float* __restrict__ b4,
    const float* __restrict__ g4, const float* __restrict__ be4,
    const float* __restrict__ w5, const float* __restrict__ b5,
    int B)
{
    extern __shared__ float sm[];
    float* W3 = sm;
    float* W4 = W3 + 16896;
    float* W5 = W4 + 8192;
    float* B3 = W5 + 64;
    float* G3 = B3 + 128;
    float* BE3= G3 + 128;
    float* B4 = BE3 + 128;
    float* G4 = B4 + 64;
    float* BE4= G4 + 64;
    float* XB = BE4 + 64;

    const int tid = threadIdx.x, lane = tid & 31, wrp = tid >> 5;
    for (int i = tid; i < 16896; i += 256) W3[i] = w3[i];
    for (int i = tid; i < 8192;  i += 256) W4[i] = w4[i];
    for (int i = tid; i < 64;    i += 256) { W5[i] = w5[i]; B4[i] = b4[i]; G4[i] = g4[i]; BE4[i] = be4[i]; }
    for (int i = tid; i < 128;   i += 256) { B3[i] = b3[i]; G3[i] = g3[i]; BE3[i] = be3[i]; }
    __syncthreads();

    float* xb = XB + wrp * 136;
    const float b5v = b5[0];

    #pragma unroll 1
    for (int i = 0; i < 4; i++) {
        int row = (blockIdx.x * 8 + wrp) * 4 + i;
        if (row >= B) break;
        __syncwarp();
        #pragma unroll
        for (int j = 0; j < 4; j++) {
            float v = dec_f(g_gf_enc[row*128 + lane + 32*j]);
            if (isnan(v)) v = NEG_FILL;
            else if (isinf(v)) v = (v > 0.f) ? 1.0e9f : NEG_FILL;
            xb[lane + 32*j] = v;
        }
        if (lane < 4) xb[128 + lane] = cond[row*4 + lane];
        __syncwarp();

        float a0 = B3[lane], a1 = B3[lane+32], a2 = B3[lane+64], a3 = B3[lane+96];
        #pragma unroll 4
        for (int k = 0; k < 132; k++) {
            float xk = xb[k];
            const float* wr = W3 + k*128;
            a0 = fmaf(xk, wr[lane],      a0);
            a1 = fmaf(xk, wr[lane+32],   a1);
            a2 = fmaf(xk, wr[lane+64],   a2);
            a3 = fmaf(xk, wr[lane+96],   a3);
        }
        float s = a0+a1+a2+a3;
        float q = a0*a0 + a1*a1 + a2*a2 + a3*a3;
        #pragma unroll
        for (int d = 16; d; d >>= 1) {
            s += __shfl_xor_sync(0xFFFFFFFFu, s, d);
            q += __shfl_xor_sync(0xFFFFFFFFu, q, d);
        }
        float m = s * (1.0f/128.0f);
        float var = fmaf(-m, m, q * (1.0f/128.0f));
        float rs = rsqrtf(var + LN_EPS);
        a0 = lrelu(fmaf((a0-m)*rs, G3[lane],    BE3[lane]));
        a1 = lrelu(fmaf((a1-m)*rs, G3[lane+32], BE3[lane+32]));
        a2 = lrelu(fmaf((a2-m)*rs, G3[lane+64], BE3[lane+64]));
        a3 = lrelu(fmaf((a3-m)*rs, G3[lane+96], BE3[lane+96]));
        __syncwarp();
        xb[lane] = a0; xb[lane+32] = a1; xb[lane+64] = a2; xb[lane+96] = a3;
        __syncwarp();

        float c0v = B4[lane], c1v = B4[lane+32];
        #pragma unroll 4
        for (int k = 0; k < 128; k++) {
            float xk = xb[k];
            c0v = fmaf(xk, W4[k*64 + lane],      c0v);
            c1v = fmaf(xk, W4[k*64 + lane + 32], c1v);
        }
        s = c0v + c1v;
        q = c0v*c0v + c1v*c1v;
        #pragma unroll
        for (int d = 16; d; d >>= 1) {
            s += __shfl_xor_sync(0xFFFFFFFFu, s, d);
            q += __shfl_xor_sync(0xFFFFFFFFu, q, d);
        }
        m = s * (1.0f/64.0f);
        var = fmaf(-m, m, q * (1.0f/64.0f));
        rs = rsqrtf(var + LN_EPS);
        c0v = lrelu(fmaf((c0v-m)*rs, G4[lane],    BE4[lane]));
        c1v = lrelu(fmaf((c1v-m)*rs, G4[lane+32], BE4[lane+32]));

        float p = c0v * W5[lane] + c1v * W5[lane+32];
        #pragma unroll
        for (int d = 16; d; d >>= 1) p += __shfl_xor_sync(0xFFFFFFFFu, p, d);
        if (lane == 0) g_score[row] = p + b5v;
    }
}

// ---------------- kernel D: EMA normalize + tanh ----------------
__global__ void k_final(float* __restrict__ out, int B) {
    __shared__ float red[1024];
    int tid = threadIdx.x;
    float s = 0.f;
    for (int i = tid; i < B; i += 1024) s += fabsf(g_score[i]);
    red[tid] = s;
    __syncthreads();
    #pragma unroll
    for (int d = 512; d; d >>= 1) {
        if (tid < d) red[tid] += red[tid + d];
        __syncthreads();
    }
    float mean  = red[0] / (float)B;
    float ema   = 0.99f + 0.01f * mean;
    float denom = fmaxf(ema, 0.1f);
    for (int i = tid; i < B; i += 1024) {
        float sc = g_score[i] / denom;
        sc = fminf(fmaxf(sc, -5.0f), 5.0f);
        out[i] = 10.0f * tanhf(sc * 0.2f);
    }
}

// ---------------- launch ----------------
extern "C" void kernel_launch(void* const* d_in, const int* in_sizes, int n_in,
                              void* d_out, int out_size) {
    const float* muons = (const float*)d_in[0];
    const int*   bidx  = (const int*)  d_in[1];
    const float* cond  = (const float*)d_in[2];
    const float* w1  = (const float*)d_in[4];
    const float* b1  = (const float*)d_in[5];
    const float* g1  = (const float*)d_in[6];
    const float* be1 = (const float*)d_in[7];
    const float* w2  = (const float*)d_in[8];
    const float* b2  = (const float*)d_in[9];
    const float* g2  = (const float*)d_in[10];
    const float* be2 = (const float*)d_in[11];
    const float* w3  = (const float*)d_in[12];
    const float* b3  = (const float*)d_in[13];
    const float* g3  = (const float*)d_in[14];
    const float* be3 = (const float*)d_in[15];
    const float* w4  = (const float*)d_in[16];
    const float* b4  = (const float*)d_in[17];
    const float* g4  = (const float*)d_in[18];
    const float* be4 = (const float*)d_in[19];
    const float* w5  = (const float*)d_in[20];
    const float* b5  = (const float*)d_in[21];

    int N = in_sizes[0] / 3;
    int B = in_sizes[2] / 4;
    if (B > MAXB) B = MAXB;

    static const size_t SMEM_DEC = (size_t)(16896 + 8192 + 64 + 128*3 + 64*3 + 8*136) * 4;
    cudaFuncSetAttribute(k_main, cudaFuncAttributeMaxDynamicSharedMemorySize, (int)SMEM_NEED);
    cudaFuncSetAttribute(k_dec,  cudaFuncAttributeMaxDynamicSharedMemorySize, (int)SMEM_DEC);

    int initN = B * 128;
    k_init<<<(initN + 255) / 256, 256>>>(initN, w1, b1);

    int nTiles = (N + ROWS - 1) / ROWS;
    int nBlocks = 2 * 148;
    if (nBlocks > nTiles) nBlocks = nTiles;
    k_main<<<nBlocks, TB, SMEM_NEED>>>(muons, bidx, cond,
                                       w1, b1, g1, be1, w2, b2, g2, be2, N, nTiles);

    int decBlocks = (B + 31) / 32;
    k_dec<<<decBlocks, 256, SMEM_DEC>>>(cond, w3, b3, g3, be3,
                                        w4, b4, g4, be4, w5, b5, B);

    k_final<<<1, 1024>>>((float*)d_out, B);
}